// round 4
// baseline (speedup 1.0000x reference)
#include <cuda_runtime.h>
#include <cstdint>
#include <cstddef>

#define NB 16
#define NS 2048
#define ND 1024
#define NM 256
#define NROWS (NB*NS)   // 32768

// ---------------- scratch (device globals: allocation-free) ----------------
__device__ float g_xm[(size_t)NROWS * NM];
__device__ float g_xf[(size_t)NROWS * NM];
__device__ float g_xu[(size_t)NROWS * NM];
__device__ float g_H [(size_t)NROWS * NM];

// ---------------- helpers ----------------
__device__ __forceinline__ uint32_t f2tf32(float x) {
    uint32_t r; asm("cvt.rna.tf32.f32 %0, %1;" : "=r"(r) : "f"(x)); return r;
}
__device__ __forceinline__ void mma_tf32(float c[4], const uint32_t a[4], const uint32_t b[2]) {
    asm volatile("mma.sync.aligned.m16n8k8.row.col.f32.tf32.tf32.f32 "
        "{%0,%1,%2,%3}, {%4,%5,%6,%7}, {%8,%9}, {%0,%1,%2,%3};"
        : "+f"(c[0]), "+f"(c[1]), "+f"(c[2]), "+f"(c[3])
        : "r"(a[0]), "r"(a[1]), "r"(a[2]), "r"(a[3]), "r"(b[0]), "r"(b[1]));
}
__device__ __forceinline__ uint32_t smem_u32(const void* p) {
    return (uint32_t)__cvta_generic_to_shared(p);
}

#define CLUSTER_ARRIVE_() asm volatile("barrier.cluster.arrive.aligned;" ::: "memory")
#define CLUSTER_WAIT_()   asm volatile("barrier.cluster.wait.aligned;"   ::: "memory")

// =====================================================================
// GEMM: C[row, n] = sum_k A[row, k] * W[n, k]   (tf32 tensor cores)
// (unchanged from R1/R2 -- known good, 445us / ~740us)
// =====================================================================
template<int MODE>
__global__ void __launch_bounds__(256) gemm_kernel(
    const float* __restrict__ X,
    const float* __restrict__ Wi, const float* __restrict__ bi,
    const float* __restrict__ Wf, const float* __restrict__ bf,
    const float* __restrict__ Wu, const float* __restrict__ bu,
    const float* __restrict__ Wo, const float* __restrict__ bo,
    float* __restrict__ out)
{
    __shared__ uint32_t As[2][128][20];
    __shared__ uint32_t Bs[2][128][20];

    const int tid  = threadIdx.x;
    const int lane = tid & 31;
    const int warp = tid >> 5;
    const int wm   = warp >> 1;   // 0..3
    const int wn   = warp & 1;    // 0..1
    const int bm   = blockIdx.x;
    const int bn   = blockIdx.y;
    const int row0 = bm * 128;
    const int col0 = bn * 128;

    const float* Bmat; int ldb; int K; int nbase;
    const float* bias = bi; float* dst = g_xm; int seg = 0;
    if (MODE == 0) {
        K = 1024;
        seg = bn >> 1;
        Bmat = (seg == 0) ? Wi : ((seg == 1) ? Wf : Wu);
        ldb  = (seg == 0) ? 1024 : 1280;
        nbase = (bn & 1) * 128;
        bias = (seg == 0) ? bi : ((seg == 1) ? bf : bu);
        dst  = (seg == 0) ? g_xm : ((seg == 1) ? g_xf : g_xu);
    } else {
        K = 1280; Bmat = Wo; ldb = 1280; nbase = col0;
    }
    const int NKT = K / 16;

    const int lr = tid >> 2;        // 0..63
    const int lc = (tid & 3) * 4;   // 0,4,8,12

    float acc[2][8][4];
    #pragma unroll
    for (int i = 0; i < 2; i++)
        #pragma unroll
        for (int j = 0; j < 8; j++)
            #pragma unroll
            for (int k = 0; k < 4; k++) acc[i][j][k] = 0.f;

    float4 ra[2], rb[2];

    auto ldgA = [&](int kt) {
        const int kk = kt * 16 + lc;
        #pragma unroll
        for (int h = 0; h < 2; ++h) {
            const int rr = row0 + lr + h * 64;
            if (MODE == 1 && kk >= 1024)
                ra[h] = *(const float4*)(g_H + (size_t)rr * NM + (kk - 1024));
            else
                ra[h] = *(const float4*)(X + (size_t)rr * ND + kk);
        }
    };
    auto ldgB = [&](int kt) {
        const int kk = kt * 16 + lc;
        #pragma unroll
        for (int h = 0; h < 2; ++h) {
            const int rr = nbase + lr + h * 64;
            rb[h] = *(const float4*)(Bmat + (size_t)rr * ldb + kk);
        }
    };
    auto stsAB = [&](int buf) {
        #pragma unroll
        for (int h = 0; h < 2; ++h) {
            uint32_t* pa = &As[buf][lr + h * 64][lc];
            pa[0] = f2tf32(ra[h].x); pa[1] = f2tf32(ra[h].y);
            pa[2] = f2tf32(ra[h].z); pa[3] = f2tf32(ra[h].w);
            uint32_t* pb = &Bs[buf][lr + h * 64][lc];
            pb[0] = f2tf32(rb[h].x); pb[1] = f2tf32(rb[h].y);
            pb[2] = f2tf32(rb[h].z); pb[3] = f2tf32(rb[h].w);
        }
    };
    auto compute = [&](int buf) {
        #pragma unroll
        for (int ks = 0; ks < 2; ++ks) {
            const int k0 = ks * 8 + (lane & 3);
            uint32_t a[2][4]; uint32_t bb[8][2];
            #pragma unroll
            for (int mf = 0; mf < 2; ++mf) {
                const int r = wm * 32 + mf * 16 + (lane >> 2);
                a[mf][0] = As[buf][r    ][k0];
                a[mf][1] = As[buf][r + 8][k0];
                a[mf][2] = As[buf][r    ][k0 + 4];
                a[mf][3] = As[buf][r + 8][k0 + 4];
            }
            #pragma unroll
            for (int nf = 0; nf < 8; ++nf) {
                const int c = wn * 64 + nf * 8 + (lane >> 2);
                bb[nf][0] = Bs[buf][c][k0];
                bb[nf][1] = Bs[buf][c][k0 + 4];
            }
            #pragma unroll
            for (int mf = 0; mf < 2; ++mf)
                #pragma unroll
                for (int nf = 0; nf < 8; ++nf)
                    mma_tf32(acc[mf][nf], a[mf], bb[nf]);
        }
    };

    ldgA(0); ldgB(0);
    stsAB(0);
    __syncthreads();
    for (int kt = 0; kt < NKT; ++kt) {
        const int buf = kt & 1;
        if (kt + 1 < NKT) { ldgA(kt + 1); ldgB(kt + 1); }
        compute(buf);
        if (kt + 1 < NKT) stsAB(buf ^ 1);
        __syncthreads();
    }

    #pragma unroll
    for (int mf = 0; mf < 2; ++mf)
        #pragma unroll
        for (int nf = 0; nf < 8; ++nf)
            #pragma unroll
            for (int h = 0; h < 2; ++h) {
                const int row = row0 + wm * 32 + mf * 16 + (lane >> 2) + h * 8;
                const int c0  = col0 + wn * 64 + nf * 8 + (lane & 3) * 2;
                float v0 = acc[mf][nf][h * 2 + 0];
                float v1 = acc[mf][nf][h * 2 + 1];
                if (MODE == 0) {
                    const int cl = c0 & 255;
                    v0 += bias[cl]; v1 += bias[cl + 1];
                    if (seg == 0) {
                        v0 = v0 / (1.f + __expf(-v0));
                        v1 = v1 / (1.f + __expf(-v1));
                    }
                    *(float2*)&dst[(size_t)row * NM + cl] = make_float2(v0, v1);
                } else {
                    v0 += bo[c0]     + X[(size_t)row * ND + c0];
                    v1 += bo[c0 + 1] + X[(size_t)row * ND + c0 + 1];
                    *(float2*)&out[(size_t)row * ND + c0] = make_float2(v0, v1);
                }
            }
}

// =====================================================================
// Recurrence v3: 16 clusters x 8 CTAs (one cluster per batch), 256 thr.
// Thread tid: row jj = tid>>3 (32 rows/CTA), k-octant kq = tid&7 (32 k).
// Each thread computes BOTH gates for its (row, k-octant): 64 FMAs.
// Reduction: 3x shfl.xor per gate (no smem, no __syncthreads).
// All 8 lanes of a row redundantly compute f, u, hn (h in register);
// lane kq sends hn to CTA kq via ONE st.shared::cluster -> 256 parallel
// stores cover all 8 CTAs' next-h buffers. One cluster barrier/step;
// input prefetch + g_H store overlapped between arrive and wait.
// =====================================================================
__global__ void __cluster_dims__(8, 1, 1) __launch_bounds__(256)
recur_kernel(const float* __restrict__ Wf, const float* __restrict__ Wu,
             float* __restrict__ hfinal)
{
    const int tid = threadIdx.x;
    const int jj  = tid >> 3;       // local row 0..31
    const int kq  = tid & 7;        // k-octant / dest CTA
    const int r   = blockIdx.x & 7; // cluster rank (row slice)
    const int b   = blockIdx.x >> 3;
    const int j   = r * 32 + jj;    // global row
    const int k0  = kq * 32;

    __shared__ alignas(16) float h_sm[2][256];

    // ---- recurrent weights: both gates, 32 k each -> 64 regs ----
    float wf[32], wu[32];
    {
        const float* pf = Wf + (size_t)j * 1280 + 1024 + k0;
        const float* pu = Wu + (size_t)j * 1280 + 1024 + k0;
        #pragma unroll
        for (int i = 0; i < 8; ++i) {
            float4 vf = *(const float4*)(pf + i * 4);
            float4 vu = *(const float4*)(pu + i * 4);
            wf[4*i+0] = vf.x; wf[4*i+1] = vf.y; wf[4*i+2] = vf.z; wf[4*i+3] = vf.w;
            wu[4*i+0] = vu.x; wu[4*i+1] = vu.y; wu[4*i+2] = vu.z; wu[4*i+3] = vu.w;
        }
    }

    // ---- remote store addresses: this thread's row in CTA kq, both buffers ----
    uint32_t rdst[2];
    {
        const uint32_t la0 = smem_u32(&h_sm[0][j]);
        const uint32_t la1 = smem_u32(&h_sm[1][j]);
        asm("mapa.shared::cluster.u32 %0, %1, %2;" : "=r"(rdst[0]) : "r"(la0), "r"(kq));
        asm("mapa.shared::cluster.u32 %0, %1, %2;" : "=r"(rdst[1]) : "r"(la1), "r"(kq));
    }

    // ---- input streams (2-deep register prefetch) ----
    const size_t base = (size_t)b * NS * NM + j;
    const float* pxf = g_xf + base;
    const float* pxu = g_xu + base;
    const float* pxm = g_xm + base;
    float xf0 = pxf[0], xf1 = pxf[NM];
    float xu0 = pxu[0], xu1 = pxu[NM];
    float xm0 = pxm[0], xm1 = pxm[NM];

    // ---- init ----
    h_sm[0][tid] = 0.f;
    float h_reg = 0.f;
    __syncthreads();
    CLUSTER_ARRIVE_();
    CLUSTER_WAIT_();

    for (int t = 0; t < NS; ++t) {
        const int buf = t & 1;

        // ---- dot over k-octant, both gates ----
        float f0 = 0.f, f1 = 0.f, f2 = 0.f, f3 = 0.f;
        float u0 = 0.f, u1 = 0.f, u2 = 0.f, u3 = 0.f;
        {
            const float4* hv = (const float4*)&h_sm[buf][k0];
            #pragma unroll
            for (int i = 0; i < 8; ++i) {
                const float4 v = hv[i];
                f0 = fmaf(wf[4*i+0], v.x, f0);
                f1 = fmaf(wf[4*i+1], v.y, f1);
                f2 = fmaf(wf[4*i+2], v.z, f2);
                f3 = fmaf(wf[4*i+3], v.w, f3);
                u0 = fmaf(wu[4*i+0], v.x, u0);
                u1 = fmaf(wu[4*i+1], v.y, u1);
                u2 = fmaf(wu[4*i+2], v.z, u2);
                u3 = fmaf(wu[4*i+3], v.w, u3);
            }
        }
        float af = (f0 + f1) + (f2 + f3);
        float au = (u0 + u1) + (u2 + u3);
        af += __shfl_xor_sync(0xffffffffu, af, 1);
        au += __shfl_xor_sync(0xffffffffu, au, 1);
        af += __shfl_xor_sync(0xffffffffu, af, 2);
        au += __shfl_xor_sync(0xffffffffu, au, 2);
        af += __shfl_xor_sync(0xffffffffu, af, 4);
        au += __shfl_xor_sync(0xffffffffu, au, 4);

        // ---- gates + state update (all 8 lanes redundantly) ----
        const float xfc = buf ? xf1 : xf0;
        const float xuc = buf ? xu1 : xu0;
        const float xmc = buf ? xm1 : xm0;
        const float f = 1.f / (1.f + __expf(-(af + xfc)));
        const float u = 1.f / (1.f + __expf(-(au + xuc)));
        const float hn = fmaf(f, h_reg, u * xmc);
        h_reg = hn;

        // ---- broadcast: one remote store per thread (dest CTA = kq) ----
        if (t + 1 < NS) {
            asm volatile("st.shared::cluster.f32 [%0], %1;"
                         :: "r"(rdst[buf ^ 1]), "f"(hn) : "memory");
        }

        CLUSTER_ARRIVE_();   // release: remote store visible after peers' wait

        // ---- overlapped with barrier: g_H store + t+2 prefetch ----
        if (kq == 0) {
            g_H[base + (size_t)t * NM] = hn;
            if (t == NS - 1 && hfinal) hfinal[b * NM + j] = hn;
        }
        if (t + 2 < NS) {
            const size_t off = (size_t)(t + 2) * NM;
            const float nf = pxf[off], nu = pxu[off], nm = pxm[off];
            if (buf) { xf1 = nf; xu1 = nu; xm1 = nm; }
            else     { xf0 = nf; xu0 = nu; xm0 = nm; }
        }

        CLUSTER_WAIT_();
    }
}

// =====================================================================
extern "C" void kernel_launch(void* const* d_in, const int* in_sizes, int n_in,
                              void* d_out, int out_size)
{
    const float* x  = (const float*)d_in[0];
    const float* Wi = (const float*)d_in[1];
    const float* bi = (const float*)d_in[2];
    const float* Wf = (const float*)d_in[3];
    const float* bf = (const float*)d_in[4];
    const float* Wu = (const float*)d_in[5];
    const float* bu = (const float*)d_in[6];
    const float* Wo = (const float*)d_in[7];
    const float* bo = (const float*)d_in[8];
    float* out = (float*)d_out;

    // Phase 1: xm / xf / xu projections (tf32 tensor cores)
    gemm_kernel<0><<<dim3(NROWS / 128, 6), 256>>>(x, Wi, bi, Wf, bf, Wu, bu, Wo, bo, out);

    // Phase 2: sequential recurrence (16 batches x 8-CTA clusters)
    float* hfinal = nullptr;
    if ((long long)out_size >= (long long)NROWS * ND + (long long)NB * NM)
        hfinal = out + (size_t)NROWS * ND;
    recur_kernel<<<128, 256>>>(Wf, Wu, hfinal);

    // Phase 3: out = x + bo + [X | H] @ Wo^T
    gemm_kernel<1><<<dim3(NROWS / 128, 8), 256>>>(x, Wi, bi, Wf, bf, Wu, bu, Wo, bo, out);
}

// round 5
// speedup vs baseline: 1.5559x; 1.5559x over previous
#include <cuda_runtime.h>
#include <cstdint>
#include <cstddef>

#define NB 16
#define NS 2048
#define ND 1024
#define NM 256
#define NROWS (NB*NS)   // 32768

// ---------------- scratch (device globals: allocation-free) ----------------
__device__ float g_xm[(size_t)NROWS * NM];
__device__ float g_xf[(size_t)NROWS * NM];
__device__ float g_xu[(size_t)NROWS * NM];
__device__ float g_H [(size_t)NROWS * NM];

// ---------------- helpers ----------------
__device__ __forceinline__ uint32_t f2tf32(float x) {
    uint32_t r; asm("cvt.rna.tf32.f32 %0, %1;" : "=r"(r) : "f"(x)); return r;
}
__device__ __forceinline__ void mma_tf32(float c[4], const uint32_t a[4], const uint32_t b[2]) {
    asm volatile("mma.sync.aligned.m16n8k8.row.col.f32.tf32.tf32.f32 "
        "{%0,%1,%2,%3}, {%4,%5,%6,%7}, {%8,%9}, {%0,%1,%2,%3};"
        : "+f"(c[0]), "+f"(c[1]), "+f"(c[2]), "+f"(c[3])
        : "r"(a[0]), "r"(a[1]), "r"(a[2]), "r"(a[3]), "r"(b[0]), "r"(b[1]));
}
__device__ __forceinline__ uint32_t smem_u32(const void* p) {
    return (uint32_t)__cvta_generic_to_shared(p);
}

#define CLUSTER_ARRIVE_() asm volatile("barrier.cluster.arrive.aligned;" ::: "memory")
#define CLUSTER_WAIT_()   asm volatile("barrier.cluster.wait.aligned;"   ::: "memory")

// =====================================================================
// GEMM: C[row, n] = sum_k A[row, k] * W[n, k]   (tf32 tensor cores)
// (unchanged -- known good: 445us / ~740us)
// =====================================================================
template<int MODE>
__global__ void __launch_bounds__(256) gemm_kernel(
    const float* __restrict__ X,
    const float* __restrict__ Wi, const float* __restrict__ bi,
    const float* __restrict__ Wf, const float* __restrict__ bf,
    const float* __restrict__ Wu, const float* __restrict__ bu,
    const float* __restrict__ Wo, const float* __restrict__ bo,
    float* __restrict__ out)
{
    __shared__ uint32_t As[2][128][20];
    __shared__ uint32_t Bs[2][128][20];

    const int tid  = threadIdx.x;
    const int lane = tid & 31;
    const int warp = tid >> 5;
    const int wm   = warp >> 1;   // 0..3
    const int wn   = warp & 1;    // 0..1
    const int bm   = blockIdx.x;
    const int bn   = blockIdx.y;
    const int row0 = bm * 128;
    const int col0 = bn * 128;

    const float* Bmat; int ldb; int K; int nbase;
    const float* bias = bi; float* dst = g_xm; int seg = 0;
    if (MODE == 0) {
        K = 1024;
        seg = bn >> 1;
        Bmat = (seg == 0) ? Wi : ((seg == 1) ? Wf : Wu);
        ldb  = (seg == 0) ? 1024 : 1280;
        nbase = (bn & 1) * 128;
        bias = (seg == 0) ? bi : ((seg == 1) ? bf : bu);
        dst  = (seg == 0) ? g_xm : ((seg == 1) ? g_xf : g_xu);
    } else {
        K = 1280; Bmat = Wo; ldb = 1280; nbase = col0;
    }
    const int NKT = K / 16;

    const int lr = tid >> 2;        // 0..63
    const int lc = (tid & 3) * 4;   // 0,4,8,12

    float acc[2][8][4];
    #pragma unroll
    for (int i = 0; i < 2; i++)
        #pragma unroll
        for (int j = 0; j < 8; j++)
            #pragma unroll
            for (int k = 0; k < 4; k++) acc[i][j][k] = 0.f;

    float4 ra[2], rb[2];

    auto ldgA = [&](int kt) {
        const int kk = kt * 16 + lc;
        #pragma unroll
        for (int h = 0; h < 2; ++h) {
            const int rr = row0 + lr + h * 64;
            if (MODE == 1 && kk >= 1024)
                ra[h] = *(const float4*)(g_H + (size_t)rr * NM + (kk - 1024));
            else
                ra[h] = *(const float4*)(X + (size_t)rr * ND + kk);
        }
    };
    auto ldgB = [&](int kt) {
        const int kk = kt * 16 + lc;
        #pragma unroll
        for (int h = 0; h < 2; ++h) {
            const int rr = nbase + lr + h * 64;
            rb[h] = *(const float4*)(Bmat + (size_t)rr * ldb + kk);
        }
    };
    auto stsAB = [&](int buf) {
        #pragma unroll
        for (int h = 0; h < 2; ++h) {
            uint32_t* pa = &As[buf][lr + h * 64][lc];
            pa[0] = f2tf32(ra[h].x); pa[1] = f2tf32(ra[h].y);
            pa[2] = f2tf32(ra[h].z); pa[3] = f2tf32(ra[h].w);
            uint32_t* pb = &Bs[buf][lr + h * 64][lc];
            pb[0] = f2tf32(rb[h].x); pb[1] = f2tf32(rb[h].y);
            pb[2] = f2tf32(rb[h].z); pb[3] = f2tf32(rb[h].w);
        }
    };
    auto compute = [&](int buf) {
        #pragma unroll
        for (int ks = 0; ks < 2; ++ks) {
            const int k0 = ks * 8 + (lane & 3);
            uint32_t a[2][4]; uint32_t bb[8][2];
            #pragma unroll
            for (int mf = 0; mf < 2; ++mf) {
                const int r = wm * 32 + mf * 16 + (lane >> 2);
                a[mf][0] = As[buf][r    ][k0];
                a[mf][1] = As[buf][r + 8][k0];
                a[mf][2] = As[buf][r    ][k0 + 4];
                a[mf][3] = As[buf][r + 8][k0 + 4];
            }
            #pragma unroll
            for (int nf = 0; nf < 8; ++nf) {
                const int c = wn * 64 + nf * 8 + (lane >> 2);
                bb[nf][0] = Bs[buf][c][k0];
                bb[nf][1] = Bs[buf][c][k0 + 4];
            }
            #pragma unroll
            for (int mf = 0; mf < 2; ++mf)
                #pragma unroll
                for (int nf = 0; nf < 8; ++nf)
                    mma_tf32(acc[mf][nf], a[mf], bb[nf]);
        }
    };

    ldgA(0); ldgB(0);
    stsAB(0);
    __syncthreads();
    for (int kt = 0; kt < NKT; ++kt) {
        const int buf = kt & 1;
        if (kt + 1 < NKT) { ldgA(kt + 1); ldgB(kt + 1); }
        compute(buf);
        if (kt + 1 < NKT) stsAB(buf ^ 1);
        __syncthreads();
    }

    #pragma unroll
    for (int mf = 0; mf < 2; ++mf)
        #pragma unroll
        for (int nf = 0; nf < 8; ++nf)
            #pragma unroll
            for (int h = 0; h < 2; ++h) {
                const int row = row0 + wm * 32 + mf * 16 + (lane >> 2) + h * 8;
                const int c0  = col0 + wn * 64 + nf * 8 + (lane & 3) * 2;
                float v0 = acc[mf][nf][h * 2 + 0];
                float v1 = acc[mf][nf][h * 2 + 1];
                if (MODE == 0) {
                    const int cl = c0 & 255;
                    v0 += bias[cl]; v1 += bias[cl + 1];
                    if (seg == 0) {
                        v0 = v0 / (1.f + __expf(-v0));
                        v1 = v1 / (1.f + __expf(-v1));
                    }
                    *(float2*)&dst[(size_t)row * NM + cl] = make_float2(v0, v1);
                } else {
                    v0 += bo[c0]     + X[(size_t)row * ND + c0];
                    v1 += bo[c0 + 1] + X[(size_t)row * ND + c0 + 1];
                    *(float2*)&out[(size_t)row * ND + c0] = make_float2(v0, v1);
                }
            }
}

// =====================================================================
// Recurrence v4: 16 clusters x 8 CTAs (one cluster per batch), 256 thr.
// Thread tid: row jj = tid>>3, lane-group kq = tid&7.
// k-mapping INTERLEAVED: thread kq owns k in {32*i + 4*kq + c}, i<8, c<4
//   -> LDS.128 addr = 16*kq + 128*i : conflict-free across the warp.
// Input streams: ONE LDG per warp per step (lane kq==0/1/2 loads
//   xf/xu/xm for its row; lanes 3..7 mirror lane 2's address = same line),
//   then 3 shfl broadcasts within each 8-lane row group.
// One remote st.shared::cluster per thread covers the 8-way h broadcast.
// One cluster barrier per step; prefetch + g_H store inside the
// arrive->wait window.
// =====================================================================
__global__ void __cluster_dims__(8, 1, 1) __launch_bounds__(256)
recur_kernel(const float* __restrict__ Wf, const float* __restrict__ Wu,
             float* __restrict__ hfinal)
{
    const int tid = threadIdx.x;
    const int jj  = tid >> 3;       // local row 0..31
    const int kq  = tid & 7;        // k interleave index / dest CTA
    const int r   = blockIdx.x & 7; // cluster rank (row slice)
    const int b   = blockIdx.x >> 3;
    const int j   = r * 32 + jj;    // global row
    const int lgbase = tid & ~7;    // first lane of this row group (warp-local ok)

    __shared__ alignas(16) float h_sm[2][256];

    // ---- recurrent weights, interleaved k-mapping: k = 32*i + 4*kq + c ----
    float wf[32], wu[32];
    {
        const float* pf = Wf + (size_t)j * 1280 + 1024 + 4 * kq;
        const float* pu = Wu + (size_t)j * 1280 + 1024 + 4 * kq;
        #pragma unroll
        for (int i = 0; i < 8; ++i) {
            float4 vf = *(const float4*)(pf + i * 32);
            float4 vu = *(const float4*)(pu + i * 32);
            wf[4*i+0] = vf.x; wf[4*i+1] = vf.y; wf[4*i+2] = vf.z; wf[4*i+3] = vf.w;
            wu[4*i+0] = vu.x; wu[4*i+1] = vu.y; wu[4*i+2] = vu.z; wu[4*i+3] = vu.w;
        }
    }

    // ---- remote store addresses: this row's slot in CTA kq, both buffers ----
    uint32_t rdst[2];
    {
        const uint32_t la0 = smem_u32(&h_sm[0][j]);
        const uint32_t la1 = smem_u32(&h_sm[1][j]);
        asm("mapa.shared::cluster.u32 %0, %1, %2;" : "=r"(rdst[0]) : "r"(la0), "r"(kq));
        asm("mapa.shared::cluster.u32 %0, %1, %2;" : "=r"(rdst[1]) : "r"(la1), "r"(kq));
    }

    // ---- per-lane stream pointer: kq==0 -> xf, 1 -> xu, >=2 -> xm ----
    const size_t base = (size_t)b * NS * NM + j;
    const float* pxs = (kq == 0) ? (g_xf + base)
                      : (kq == 1) ? (g_xu + base)
                      :             (g_xm + base);
    // 2-deep register prefetch of this lane's stream
    float v0 = pxs[0], v1 = pxs[NM];

    // ---- init ----
    h_sm[0][tid] = 0.f;
    float h_reg = 0.f;
    __syncthreads();
    CLUSTER_ARRIVE_();
    CLUSTER_WAIT_();

    const unsigned FULL = 0xffffffffu;

    for (int t = 0; t < NS; ++t) {
        const int buf = t & 1;

        // ---- dot over interleaved k set, both gates (conflict-free LDS) ----
        float f0 = 0.f, f1 = 0.f, f2 = 0.f, f3 = 0.f;
        float u0 = 0.f, u1 = 0.f, u2 = 0.f, u3 = 0.f;
        {
            const float4* hv = (const float4*)&h_sm[buf][4 * kq];
            #pragma unroll
            for (int i = 0; i < 8; ++i) {
                const float4 v = hv[i * 8];           // addr = 16*kq + 128*i
                f0 = fmaf(wf[4*i+0], v.x, f0);
                f1 = fmaf(wf[4*i+1], v.y, f1);
                f2 = fmaf(wf[4*i+2], v.z, f2);
                f3 = fmaf(wf[4*i+3], v.w, f3);
                u0 = fmaf(wu[4*i+0], v.x, u0);
                u1 = fmaf(wu[4*i+1], v.y, u1);
                u2 = fmaf(wu[4*i+2], v.z, u2);
                u3 = fmaf(wu[4*i+3], v.w, u3);
            }
        }
        float af = (f0 + f1) + (f2 + f3);
        float au = (u0 + u1) + (u2 + u3);
        af += __shfl_xor_sync(FULL, af, 1);
        au += __shfl_xor_sync(FULL, au, 1);
        af += __shfl_xor_sync(FULL, af, 2);
        au += __shfl_xor_sync(FULL, au, 2);
        af += __shfl_xor_sync(FULL, af, 4);
        au += __shfl_xor_sync(FULL, au, 4);

        // ---- broadcast this step's inputs within the row group ----
        const float vc  = buf ? v1 : v0;
        const float xfc = __shfl_sync(FULL, vc, lgbase + 0);
        const float xuc = __shfl_sync(FULL, vc, lgbase + 1);
        const float xmc = __shfl_sync(FULL, vc, lgbase + 2);

        // ---- gates + state update (all 8 lanes redundantly) ----
        const float f = 1.f / (1.f + __expf(-(af + xfc)));
        const float u = 1.f / (1.f + __expf(-(au + xuc)));
        const float hn = fmaf(f, h_reg, u * xmc);
        h_reg = hn;

        // ---- broadcast: one remote store per thread (dest CTA = kq) ----
        if (t + 1 < NS) {
            asm volatile("st.shared::cluster.f32 [%0], %1;"
                         :: "r"(rdst[buf ^ 1]), "f"(hn) : "memory");
        }

        CLUSTER_ARRIVE_();   // release: remote stores visible after peers' wait

        // ---- overlapped with barrier: g_H store + t+2 stream refill ----
        if (kq == 0) {
            g_H[base + (size_t)t * NM] = hn;
            if (t == NS - 1 && hfinal) hfinal[b * NM + j] = hn;
        }
        if (t + 2 < NS) {
            const float nv = pxs[(size_t)(t + 2) * NM];  // 1 LDG / warp
            if (buf) v1 = nv; else v0 = nv;
        }

        CLUSTER_WAIT_();
    }
}

// =====================================================================
extern "C" void kernel_launch(void* const* d_in, const int* in_sizes, int n_in,
                              void* d_out, int out_size)
{
    const float* x  = (const float*)d_in[0];
    const float* Wi = (const float*)d_in[1];
    const float* bi = (const float*)d_in[2];
    const float* Wf = (const float*)d_in[3];
    const float* bf = (const float*)d_in[4];
    const float* Wu = (const float*)d_in[5];
    const float* bu = (const float*)d_in[6];
    const float* Wo = (const float*)d_in[7];
    const float* bo = (const float*)d_in[8];
    float* out = (float*)d_out;

    // Phase 1: xm / xf / xu projections (tf32 tensor cores)
    gemm_kernel<0><<<dim3(NROWS / 128, 6), 256>>>(x, Wi, bi, Wf, bf, Wu, bu, Wo, bo, out);

    // Phase 2: sequential recurrence (16 batches x 8-CTA clusters)
    float* hfinal = nullptr;
    if ((long long)out_size >= (long long)NROWS * ND + (long long)NB * NM)
        hfinal = out + (size_t)NROWS * ND;
    recur_kernel<<<128, 256>>>(Wf, Wu, hfinal);

    // Phase 3: out = x + bo + [X | H] @ Wo^T
    gemm_kernel<1><<<dim3(NROWS / 128, 8), 256>>>(x, Wi, bi, Wf, bf, Wu, bu, Wo, bo, out);
}

// round 7
// speedup vs baseline: 1.9244x; 1.2368x over previous
#include <cuda_runtime.h>
#include <cstdint>
#include <cstddef>

#define NB 16
#define NS 2048
#define ND 1024
#define NM 256
#define NROWS (NB*NS)   // 32768

// ---------------- scratch (device globals: allocation-free) ----------------
// interleaved gate inputs: g_xg[(row*NM + m)*4 + {0:xf, 1:xu, 2:xm, 3:pad}]
__device__ __align__(16) float g_xg[(size_t)NROWS * NM * 4];
__device__ __align__(16) float g_H [(size_t)NROWS * NM];

// ---------------- helpers ----------------
__device__ __forceinline__ uint32_t f2tf32(float x) {
    uint32_t r; asm("cvt.rna.tf32.f32 %0, %1;" : "=r"(r) : "f"(x)); return r;
}
__device__ __forceinline__ void mma_tf32(float c[4], const uint32_t a[4], const uint32_t b[2]) {
    asm volatile("mma.sync.aligned.m16n8k8.row.col.f32.tf32.tf32.f32 "
        "{%0,%1,%2,%3}, {%4,%5,%6,%7}, {%8,%9}, {%0,%1,%2,%3};"
        : "+f"(c[0]), "+f"(c[1]), "+f"(c[2]), "+f"(c[3])
        : "r"(a[0]), "r"(a[1]), "r"(a[2]), "r"(a[3]), "r"(b[0]), "r"(b[1]));
}
__device__ __forceinline__ uint32_t smem_u32(const void* p) {
    return (uint32_t)__cvta_generic_to_shared(p);
}
__device__ __forceinline__ unsigned long long pack2(float lo, float hi) {
    unsigned long long r;
    asm("mov.b64 %0, {%1, %2};" : "=l"(r) : "f"(lo), "f"(hi));
    return r;
}
__device__ __forceinline__ void unpack2(float& lo, float& hi, unsigned long long v) {
    asm("mov.b64 {%0, %1}, %2;" : "=f"(lo), "=f"(hi) : "l"(v));
}
#define FFMA2(acc, a, b) \
    asm("fma.rn.f32x2 %0, %1, %2, %0;" : "+l"(acc) : "l"(a), "l"(b))

#define CLUSTER_ARRIVE_() asm volatile("barrier.cluster.arrive.aligned;" ::: "memory")
#define CLUSTER_WAIT_()   asm volatile("barrier.cluster.wait.aligned;"   ::: "memory")

// =====================================================================
// GEMM: C[row, n] = sum_k A[row, k] * W[n, k]   (tf32 tensor cores)
// MODE 0 epilogue writes interleaved g_xg (s: xf=0, xu=1, xm=2).
// MODE 1: out = x + bo + [X | H] @ Wo^T
// =====================================================================
template<int MODE>
__global__ void __launch_bounds__(256) gemm_kernel(
    const float* __restrict__ X,
    const float* __restrict__ Wi, const float* __restrict__ bi,
    const float* __restrict__ Wf, const float* __restrict__ bf,
    const float* __restrict__ Wu, const float* __restrict__ bu,
    const float* __restrict__ Wo, const float* __restrict__ bo,
    float* __restrict__ out)
{
    __shared__ uint32_t As[2][128][20];
    __shared__ uint32_t Bs[2][128][20];

    const int tid  = threadIdx.x;
    const int lane = tid & 31;
    const int warp = tid >> 5;
    const int wm   = warp >> 1;   // 0..3
    const int wn   = warp & 1;    // 0..1
    const int bm   = blockIdx.x;
    const int bn   = blockIdx.y;
    const int row0 = bm * 128;
    const int col0 = bn * 128;

    const float* Bmat; int ldb; int K; int nbase;
    const float* bias = bi; int seg = 0;
    if (MODE == 0) {
        K = 1024;
        seg = bn >> 1;
        Bmat = (seg == 0) ? Wi : ((seg == 1) ? Wf : Wu);
        ldb  = (seg == 0) ? 1024 : 1280;
        nbase = (bn & 1) * 128;
        bias = (seg == 0) ? bi : ((seg == 1) ? bf : bu);
    } else {
        K = 1280; Bmat = Wo; ldb = 1280; nbase = col0;
    }
    const int NKT = K / 16;

    const int lr = tid >> 2;        // 0..63
    const int lc = (tid & 3) * 4;   // 0,4,8,12

    float acc[2][8][4];
    #pragma unroll
    for (int i = 0; i < 2; i++)
        #pragma unroll
        for (int j = 0; j < 8; j++)
            #pragma unroll
            for (int k = 0; k < 4; k++) acc[i][j][k] = 0.f;

    float4 ra[2], rb[2];

    auto ldgA = [&](int kt) {
        const int kk = kt * 16 + lc;
        #pragma unroll
        for (int h = 0; h < 2; ++h) {
            const int rr = row0 + lr + h * 64;
            if (MODE == 1 && kk >= 1024)
                ra[h] = *(const float4*)(g_H + (size_t)rr * NM + (kk - 1024));
            else
                ra[h] = *(const float4*)(X + (size_t)rr * ND + kk);
        }
    };
    auto ldgB = [&](int kt) {
        const int kk = kt * 16 + lc;
        #pragma unroll
        for (int h = 0; h < 2; ++h) {
            const int rr = nbase + lr + h * 64;
            rb[h] = *(const float4*)(Bmat + (size_t)rr * ldb + kk);
        }
    };
    auto stsAB = [&](int buf) {
        #pragma unroll
        for (int h = 0; h < 2; ++h) {
            uint32_t* pa = &As[buf][lr + h * 64][lc];
            pa[0] = f2tf32(ra[h].x); pa[1] = f2tf32(ra[h].y);
            pa[2] = f2tf32(ra[h].z); pa[3] = f2tf32(ra[h].w);
            uint32_t* pb = &Bs[buf][lr + h * 64][lc];
            pb[0] = f2tf32(rb[h].x); pb[1] = f2tf32(rb[h].y);
            pb[2] = f2tf32(rb[h].z); pb[3] = f2tf32(rb[h].w);
        }
    };
    auto compute = [&](int buf) {
        #pragma unroll
        for (int ks = 0; ks < 2; ++ks) {
            const int k0 = ks * 8 + (lane & 3);
            uint32_t a[2][4]; uint32_t bb[8][2];
            #pragma unroll
            for (int mf = 0; mf < 2; ++mf) {
                const int r = wm * 32 + mf * 16 + (lane >> 2);
                a[mf][0] = As[buf][r    ][k0];
                a[mf][1] = As[buf][r + 8][k0];
                a[mf][2] = As[buf][r    ][k0 + 4];
                a[mf][3] = As[buf][r + 8][k0 + 4];
            }
            #pragma unroll
            for (int nf = 0; nf < 8; ++nf) {
                const int c = wn * 64 + nf * 8 + (lane >> 2);
                bb[nf][0] = Bs[buf][c][k0];
                bb[nf][1] = Bs[buf][c][k0 + 4];
            }
            #pragma unroll
            for (int mf = 0; mf < 2; ++mf)
                #pragma unroll
                for (int nf = 0; nf < 8; ++nf)
                    mma_tf32(acc[mf][nf], a[mf], bb[nf]);
        }
    };

    ldgA(0); ldgB(0);
    stsAB(0);
    __syncthreads();
    for (int kt = 0; kt < NKT; ++kt) {
        const int buf = kt & 1;
        if (kt + 1 < NKT) { ldgA(kt + 1); ldgB(kt + 1); }
        compute(buf);
        if (kt + 1 < NKT) stsAB(buf ^ 1);
        __syncthreads();
    }

    // epilogue
    const int s_idx = (MODE == 0) ? ((seg == 1) ? 0 : (seg == 2) ? 1 : 2) : 0;
    #pragma unroll
    for (int mf = 0; mf < 2; ++mf)
        #pragma unroll
        for (int nf = 0; nf < 8; ++nf)
            #pragma unroll
            for (int h = 0; h < 2; ++h) {
                const int row = row0 + wm * 32 + mf * 16 + (lane >> 2) + h * 8;
                const int c0  = col0 + wn * 64 + nf * 8 + (lane & 3) * 2;
                float v0 = acc[mf][nf][h * 2 + 0];
                float v1 = acc[mf][nf][h * 2 + 1];
                if (MODE == 0) {
                    const int cl = c0 & 255;
                    v0 += bias[cl]; v1 += bias[cl + 1];
                    if (seg == 0) {   // silu for xm
                        v0 = v0 / (1.f + __expf(-v0));
                        v1 = v1 / (1.f + __expf(-v1));
                    }
                    g_xg[((size_t)row * NM + cl    ) * 4 + s_idx] = v0;
                    g_xg[((size_t)row * NM + cl + 1) * 4 + s_idx] = v1;
                } else {
                    v0 += bo[c0]     + X[(size_t)row * ND + c0];
                    v1 += bo[c0 + 1] + X[(size_t)row * ND + c0 + 1];
                    *(float2*)&out[(size_t)row * ND + c0] = make_float2(v0, v1);
                }
            }
}

// =====================================================================
// Recurrence v6 = R4's proven barrier.cluster loop +
//   (a) packed f32x2 FFMA2 math (2 MACs/instr, full fp32 precision)
//   (b) ONE predicated float4 LDG per 8-lane row group from g_xg
// Thread tid: row jj = tid>>3, k-interleave kq = tid&7 (k = 32i+4kq+c).
// One remote st.shared::cluster per thread broadcasts h; one cluster
// barrier per step with g_H store + t+2 prefetch in the arrive->wait gap.
// =====================================================================
__global__ void __cluster_dims__(8, 1, 1) __launch_bounds__(256)
recur_kernel(const float* __restrict__ Wf, const float* __restrict__ Wu,
             float* __restrict__ hfinal)
{
    const int tid = threadIdx.x;
    const int jj  = tid >> 3;          // local row 0..31
    const int kq  = tid & 7;           // k interleave / dest CTA
    const int r   = blockIdx.x & 7;    // cluster rank (row slice)
    const int b   = blockIdx.x >> 3;
    const int j   = r * 32 + jj;       // global row
    const int lg  = (tid & 31) & ~7;   // row-group leader lane in warp

    __shared__ alignas(16) float h_sm[2][256];

    // ---- recurrent weights, interleaved k = 32*i + 4*kq + c, packed f32x2 ----
    unsigned long long wf2[16], wu2[16];
    {
        const float* pf = Wf + (size_t)j * 1280 + 1024 + 4 * kq;
        const float* pu = Wu + (size_t)j * 1280 + 1024 + 4 * kq;
        #pragma unroll
        for (int i = 0; i < 8; ++i) {
            float4 vf = *(const float4*)(pf + i * 32);
            float4 vu = *(const float4*)(pu + i * 32);
            wf2[2*i+0] = pack2(vf.x, vf.y);
            wf2[2*i+1] = pack2(vf.z, vf.w);
            wu2[2*i+0] = pack2(vu.x, vu.y);
            wu2[2*i+1] = pack2(vu.z, vu.w);
        }
    }

    // ---- remote store addresses: this row's slot in CTA kq, both buffers ----
    uint32_t rdst[2];
    {
        const uint32_t la0 = smem_u32(&h_sm[0][j]);
        const uint32_t la1 = smem_u32(&h_sm[1][j]);
        asm("mapa.shared::cluster.u32 %0, %1, %2;" : "=r"(rdst[0]) : "r"(la0), "r"(kq));
        asm("mapa.shared::cluster.u32 %0, %1, %2;" : "=r"(rdst[1]) : "r"(la1), "r"(kq));
    }

    // ---- local h read base (both buffers), conflict-free 16B interleave ----
    const uint32_t ha[2] = { smem_u32(&h_sm[0][4 * kq]), smem_u32(&h_sm[1][4 * kq]) };

    // ---- input stream: one float4 per row group (leader lane), 2-deep ----
    const float4* pxg = (const float4*)g_xg + (size_t)b * NS * NM + j;
    float4 in0 = make_float4(0.f, 0.f, 0.f, 0.f), in1 = in0;
    if (kq == 0) { in0 = pxg[0]; in1 = pxg[NM]; }

    // ---- init ----
    h_sm[0][tid] = 0.f;
    float h_reg = 0.f;
    __syncthreads();
    CLUSTER_ARRIVE_();
    CLUSTER_WAIT_();

    const unsigned FULL = 0xffffffffu;

    for (int t = 0; t < NS; ++t) {
        const int buf = t & 1;

        // ---- dot over interleaved k set, both gates, packed f32x2 ----
        unsigned long long fa = 0ull, fb = 0ull, ua = 0ull, ub = 0ull;
        {
            const uint32_t hb = ha[buf];
            #pragma unroll
            for (int i = 0; i < 8; ++i) {
                unsigned long long h01, h23;
                asm volatile("ld.shared.v2.b64 {%0, %1}, [%2];"
                             : "=l"(h01), "=l"(h23) : "r"(hb + i * 128));
                FFMA2(fa, wf2[2*i+0], h01);
                FFMA2(fb, wf2[2*i+1], h23);
                FFMA2(ua, wu2[2*i+0], h01);
                FFMA2(ub, wu2[2*i+1], h23);
            }
        }
        float f_lo, f_hi, u_lo, u_hi, t_lo, t_hi;
        unpack2(f_lo, f_hi, fa); unpack2(t_lo, t_hi, fb);
        float af = (f_lo + f_hi) + (t_lo + t_hi);
        unpack2(u_lo, u_hi, ua); unpack2(t_lo, t_hi, ub);
        float au = (u_lo + u_hi) + (t_lo + t_hi);

        af += __shfl_xor_sync(FULL, af, 1);
        au += __shfl_xor_sync(FULL, au, 1);
        af += __shfl_xor_sync(FULL, af, 2);
        au += __shfl_xor_sync(FULL, au, 2);
        af += __shfl_xor_sync(FULL, af, 4);
        au += __shfl_xor_sync(FULL, au, 4);

        // ---- broadcast this step's inputs within the row group ----
        const float4 vc = buf ? in1 : in0;
        const float xfc = __shfl_sync(FULL, vc.x, lg);
        const float xuc = __shfl_sync(FULL, vc.y, lg);
        const float xmc = __shfl_sync(FULL, vc.z, lg);

        // ---- gates + state update (all 8 lanes redundantly) ----
        const float f = 1.f / (1.f + __expf(-(af + xfc)));
        const float u = 1.f / (1.f + __expf(-(au + xuc)));
        const float hn = fmaf(f, h_reg, u * xmc);
        h_reg = hn;

        // ---- publish next h: one remote store per thread (dest CTA = kq) ----
        if (t + 1 < NS) {
            asm volatile("st.shared::cluster.f32 [%0], %1;"
                         :: "r"(rdst[buf ^ 1]), "f"(hn) : "memory");
        }

        CLUSTER_ARRIVE_();   // release: remote stores visible after peers' wait

        // ---- overlapped with barrier: g_H store + t+2 stream refill ----
        if (kq == 0) {
            g_H[(size_t)(b * NS + t) * NM + j] = hn;
            if (t == NS - 1 && hfinal) hfinal[b * NM + j] = hn;
            if (t + 2 < NS) {
                const float4 nv = pxg[(size_t)(t + 2) * NM];
                if (buf) in1 = nv; else in0 = nv;
            }
        }

        CLUSTER_WAIT_();
    }
}

// =====================================================================
extern "C" void kernel_launch(void* const* d_in, const int* in_sizes, int n_in,
                              void* d_out, int out_size)
{
    const float* x  = (const float*)d_in[0];
    const float* Wi = (const float*)d_in[1];
    const float* bi = (const float*)d_in[2];
    const float* Wf = (const float*)d_in[3];
    const float* bf = (const float*)d_in[4];
    const float* Wu = (const float*)d_in[5];
    const float* bu = (const float*)d_in[6];
    const float* Wo = (const float*)d_in[7];
    const float* bo = (const float*)d_in[8];
    float* out = (float*)d_out;

    // Phase 1: xm / xf / xu projections (tf32 tensor cores) -> interleaved g_xg
    gemm_kernel<0><<<dim3(NROWS / 128, 6), 256>>>(x, Wi, bi, Wf, bf, Wu, bu, Wo, bo, out);

    // Phase 2: sequential recurrence (16 batches x 8-CTA clusters)
    float* hfinal = nullptr;
    if ((long long)out_size >= (long long)NROWS * ND + (long long)NB * NM)
        hfinal = out + (size_t)NROWS * ND;
    recur_kernel<<<128, 256>>>(Wf, Wu, hfinal);

    // Phase 3: out = x + bo + [X | H] @ Wo^T
    gemm_kernel<1><<<dim3(NROWS / 128, 8), 256>>>(x, Wi, bi, Wf, bf, Wu, bu, Wo, bo, out);
}

// round 8
// speedup vs baseline: 1.9743x; 1.0259x over previous
#include <cuda_runtime.h>
#include <cstdint>
#include <cstddef>

#define NB 16
#define NS 2048
#define ND 1024
#define NM 256
#define NROWS (NB*NS)   // 32768

// ---------------- scratch (device globals: allocation-free) ----------------
__device__ __align__(16) float g_xf[(size_t)NROWS * NM];
__device__ __align__(16) float g_xu[(size_t)NROWS * NM];
__device__ __align__(16) float g_xm[(size_t)NROWS * NM];
__device__ __align__(16) float g_H [(size_t)NROWS * NM];

// ---------------- helpers ----------------
__device__ __forceinline__ uint32_t f2tf32(float x) {
    uint32_t r; asm("cvt.rna.tf32.f32 %0, %1;" : "=r"(r) : "f"(x)); return r;
}
__device__ __forceinline__ void mma_tf32(float c[4], const uint32_t a[4], const uint32_t b[2]) {
    asm volatile("mma.sync.aligned.m16n8k8.row.col.f32.tf32.tf32.f32 "
        "{%0,%1,%2,%3}, {%4,%5,%6,%7}, {%8,%9}, {%0,%1,%2,%3};"
        : "+f"(c[0]), "+f"(c[1]), "+f"(c[2]), "+f"(c[3])
        : "r"(a[0]), "r"(a[1]), "r"(a[2]), "r"(a[3]), "r"(b[0]), "r"(b[1]));
}
__device__ __forceinline__ uint32_t smem_u32(const void* p) {
    return (uint32_t)__cvta_generic_to_shared(p);
}
__device__ __forceinline__ unsigned long long pack2(float lo, float hi) {
    unsigned long long r;
    asm("mov.b64 %0, {%1, %2};" : "=l"(r) : "f"(lo), "f"(hi));
    return r;
}
__device__ __forceinline__ void unpack2(float& lo, float& hi, unsigned long long v) {
    asm("mov.b64 {%0, %1}, %2;" : "=f"(lo), "=f"(hi) : "l"(v));
}
#define FFMA2(acc, a, b) \
    asm("fma.rn.f32x2 %0, %1, %2, %0;" : "+l"(acc) : "l"(a), "l"(b))

#define CLUSTER_SYNC_() do {                                          \
    asm volatile("barrier.cluster.arrive.aligned;" ::: "memory");     \
    asm volatile("barrier.cluster.wait.aligned;"   ::: "memory");     \
} while (0)

#define MBAR_INIT(addr, cnt) \
    asm volatile("mbarrier.init.shared.b64 [%0], %1;" :: "r"(addr), "r"(cnt) : "memory")

// acquire-at-cluster-scope parity wait (architected HW sleep/wake)
#define MBAR_WAIT_CL(addr, par) do {                                         \
    uint32_t _m = (addr); uint32_t _p = (par); uint32_t _done;               \
    asm volatile(                                                            \
        "{\n\t.reg .pred p;\n\t"                                             \
        "mbarrier.try_wait.parity.acquire.cluster.shared::cta.b64 p, [%1], %2;\n\t" \
        "selp.b32 %0, 1, 0, p;\n\t}"                                         \
        : "=r"(_done) : "r"(_m), "r"(_p) : "memory");                        \
    if (!_done) {                                                            \
        asm volatile(                                                        \
            "{\n\t.reg .pred P1;\n\t"                                        \
            "WAIT_LOOP_%=:\n\t"                                              \
            "mbarrier.try_wait.parity.acquire.cluster.shared::cta.b64 P1, [%0], %1, 0x989680;\n\t" \
            "@P1 bra.uni WAIT_DONE_%=;\n\t"                                  \
            "bra.uni WAIT_LOOP_%=;\n\t"                                      \
            "WAIT_DONE_%=:\n\t}"                                             \
            :: "r"(_m), "r"(_p) : "memory");                                 \
    }                                                                        \
} while (0)

// =====================================================================
// GEMM: C[row, n] = sum_k A[row, k] * W[n, k]   (tf32 tensor cores)
// MODE 0: N=768 over {Wi, Wf[:, :d], Wu[:, :d]}; +bias, silu for xm;
//         -> g_xm / g_xf / g_xu   (coalesced float2 stores)
// MODE 1: out = x + bo + [X | H] @ Wo^T
// =====================================================================
template<int MODE>
__global__ void __launch_bounds__(256) gemm_kernel(
    const float* __restrict__ X,
    const float* __restrict__ Wi, const float* __restrict__ bi,
    const float* __restrict__ Wf, const float* __restrict__ bf,
    const float* __restrict__ Wu, const float* __restrict__ bu,
    const float* __restrict__ Wo, const float* __restrict__ bo,
    float* __restrict__ out)
{
    __shared__ uint32_t As[2][128][20];
    __shared__ uint32_t Bs[2][128][20];

    const int tid  = threadIdx.x;
    const int lane = tid & 31;
    const int warp = tid >> 5;
    const int wm   = warp >> 1;   // 0..3
    const int wn   = warp & 1;    // 0..1
    const int bm   = blockIdx.x;
    const int bn   = blockIdx.y;
    const int row0 = bm * 128;
    const int col0 = bn * 128;

    const float* Bmat; int ldb; int K; int nbase;
    const float* bias = bi; float* dst = g_xm; int seg = 0;
    if (MODE == 0) {
        K = 1024;
        seg = bn >> 1;
        Bmat = (seg == 0) ? Wi : ((seg == 1) ? Wf : Wu);
        ldb  = (seg == 0) ? 1024 : 1280;
        nbase = (bn & 1) * 128;
        bias = (seg == 0) ? bi : ((seg == 1) ? bf : bu);
        dst  = (seg == 0) ? g_xm : ((seg == 1) ? g_xf : g_xu);
    } else {
        K = 1280; Bmat = Wo; ldb = 1280; nbase = col0;
    }
    const int NKT = K / 16;

    const int lr = tid >> 2;        // 0..63
    const int lc = (tid & 3) * 4;   // 0,4,8,12

    float acc[2][8][4];
    #pragma unroll
    for (int i = 0; i < 2; i++)
        #pragma unroll
        for (int j = 0; j < 8; j++)
            #pragma unroll
            for (int k = 0; k < 4; k++) acc[i][j][k] = 0.f;

    float4 ra[2], rb[2];

    auto ldgA = [&](int kt) {
        const int kk = kt * 16 + lc;
        #pragma unroll
        for (int h = 0; h < 2; ++h) {
            const int rr = row0 + lr + h * 64;
            if (MODE == 1 && kk >= 1024)
                ra[h] = *(const float4*)(g_H + (size_t)rr * NM + (kk - 1024));
            else
                ra[h] = *(const float4*)(X + (size_t)rr * ND + kk);
        }
    };
    auto ldgB = [&](int kt) {
        const int kk = kt * 16 + lc;
        #pragma unroll
        for (int h = 0; h < 2; ++h) {
            const int rr = nbase + lr + h * 64;
            rb[h] = *(const float4*)(Bmat + (size_t)rr * ldb + kk);
        }
    };
    auto stsAB = [&](int buf) {
        #pragma unroll
        for (int h = 0; h < 2; ++h) {
            uint32_t* pa = &As[buf][lr + h * 64][lc];
            pa[0] = f2tf32(ra[h].x); pa[1] = f2tf32(ra[h].y);
            pa[2] = f2tf32(ra[h].z); pa[3] = f2tf32(ra[h].w);
            uint32_t* pb = &Bs[buf][lr + h * 64][lc];
            pb[0] = f2tf32(rb[h].x); pb[1] = f2tf32(rb[h].y);
            pb[2] = f2tf32(rb[h].z); pb[3] = f2tf32(rb[h].w);
        }
    };
    auto compute = [&](int buf) {
        #pragma unroll
        for (int ks = 0; ks < 2; ++ks) {
            const int k0 = ks * 8 + (lane & 3);
            uint32_t a[2][4]; uint32_t bb[8][2];
            #pragma unroll
            for (int mf = 0; mf < 2; ++mf) {
                const int r = wm * 32 + mf * 16 + (lane >> 2);
                a[mf][0] = As[buf][r    ][k0];
                a[mf][1] = As[buf][r + 8][k0];
                a[mf][2] = As[buf][r    ][k0 + 4];
                a[mf][3] = As[buf][r + 8][k0 + 4];
            }
            #pragma unroll
            for (int nf = 0; nf < 8; ++nf) {
                const int c = wn * 64 + nf * 8 + (lane >> 2);
                bb[nf][0] = Bs[buf][c][k0];
                bb[nf][1] = Bs[buf][c][k0 + 4];
            }
            #pragma unroll
            for (int mf = 0; mf < 2; ++mf)
                #pragma unroll
                for (int nf = 0; nf < 8; ++nf)
                    mma_tf32(acc[mf][nf], a[mf], bb[nf]);
        }
    };

    ldgA(0); ldgB(0);
    stsAB(0);
    __syncthreads();
    for (int kt = 0; kt < NKT; ++kt) {
        const int buf = kt & 1;
        if (kt + 1 < NKT) { ldgA(kt + 1); ldgB(kt + 1); }
        compute(buf);
        if (kt + 1 < NKT) stsAB(buf ^ 1);
        __syncthreads();
    }

    #pragma unroll
    for (int mf = 0; mf < 2; ++mf)
        #pragma unroll
        for (int nf = 0; nf < 8; ++nf)
            #pragma unroll
            for (int h = 0; h < 2; ++h) {
                const int row = row0 + wm * 32 + mf * 16 + (lane >> 2) + h * 8;
                const int c0  = col0 + wn * 64 + nf * 8 + (lane & 3) * 2;
                float v0 = acc[mf][nf][h * 2 + 0];
                float v1 = acc[mf][nf][h * 2 + 1];
                if (MODE == 0) {
                    const int cl = c0 & 255;
                    v0 += bias[cl]; v1 += bias[cl + 1];
                    if (seg == 0) {   // silu for xm
                        v0 = v0 / (1.f + __expf(-v0));
                        v1 = v1 / (1.f + __expf(-v1));
                    }
                    *(float2*)&dst[(size_t)row * NM + cl] = make_float2(v0, v1);
                } else {
                    v0 += bo[c0]     + X[(size_t)row * ND + c0];
                    v1 += bo[c0 + 1] + X[(size_t)row * ND + c0 + 1];
                    *(float2*)&out[(size_t)row * ND + c0] = make_float2(v0, v1);
                }
            }
}

// =====================================================================
// Recurrence v7 = R6 compute core (FFMA2 dot, interleaved k, one remote
// st per thread) with the cluster barrier replaced by double-buffered
// COUNT-mbarriers (count = 8, one arrive per producer CTA per step):
//   step t: wait mbar[p] (acquire.cluster)  [t>0]
//           dot(h_sm[p]) -> gates -> hn
//           st.shared::cluster hn -> peers' h_sm[p^1]
//           __syncthreads
//           tid<8: fence.acq_rel.cluster; arrive peer tid's mbar[p^1]
//           tail: g_H store + t+2 input prefetch (overlaps peers' waits)
// Safety: a producer's arrive happens after its reads of h_sm[p^1]'s
// previous contents, and it can only advance after collecting all 8
// arrivals itself -> skew bounded to one phase, absorbed by the double
// buffer. Arrive/wait counts balance exactly (1024/1023 phases).
// =====================================================================
__global__ void __cluster_dims__(8, 1, 1) __launch_bounds__(256)
recur_kernel(const float* __restrict__ Wf, const float* __restrict__ Wu,
             float* __restrict__ hfinal)
{
    const int tid = threadIdx.x;
    const int jj  = tid >> 3;          // local row 0..31
    const int kq  = tid & 7;           // k interleave / dest CTA
    const int r   = blockIdx.x & 7;    // cluster rank (row slice)
    const int b   = blockIdx.x >> 3;
    const int j   = r * 32 + jj;       // global row
    const int lg  = (tid & 31) & ~7;   // row-group leader lane in warp

    __shared__ alignas(16) float h_sm[2][256];
    __shared__ alignas(8) unsigned long long mbar[2];

    // ---- recurrent weights, interleaved k = 32*i + 4*kq + c, packed f32x2 ----
    unsigned long long wf2[16], wu2[16];
    {
        const float* pf = Wf + (size_t)j * 1280 + 1024 + 4 * kq;
        const float* pu = Wu + (size_t)j * 1280 + 1024 + 4 * kq;
        #pragma unroll
        for (int i = 0; i < 8; ++i) {
            float4 vf = *(const float4*)(pf + i * 32);
            float4 vu = *(const float4*)(pu + i * 32);
            wf2[2*i+0] = pack2(vf.x, vf.y);
            wf2[2*i+1] = pack2(vf.z, vf.w);
            wu2[2*i+0] = pack2(vu.x, vu.y);
            wu2[2*i+1] = pack2(vu.z, vu.w);
        }
    }

    // ---- remote h-store addresses: this row's slot in CTA kq, both buffers ----
    uint32_t rdst[2];
    {
        const uint32_t la0 = smem_u32(&h_sm[0][j]);
        const uint32_t la1 = smem_u32(&h_sm[1][j]);
        asm("mapa.shared::cluster.u32 %0, %1, %2;" : "=r"(rdst[0]) : "r"(la0), "r"(kq));
        asm("mapa.shared::cluster.u32 %0, %1, %2;" : "=r"(rdst[1]) : "r"(la1), "r"(kq));
    }

    // ---- remote mbar addresses (tid<8: thread tid arrives on peer tid) ----
    uint32_t rmb[2] = {0u, 0u};
    if (tid < 8) {
        const uint32_t lm0 = smem_u32(&mbar[0]);
        const uint32_t lm1 = smem_u32(&mbar[1]);
        asm("mapa.shared::cluster.u32 %0, %1, %2;" : "=r"(rmb[0]) : "r"(lm0), "r"(tid));
        asm("mapa.shared::cluster.u32 %0, %1, %2;" : "=r"(rmb[1]) : "r"(lm1), "r"(tid));
    }

    // ---- local h read base (both buffers), conflict-free 16B interleave ----
    const uint32_t ha[2] = { smem_u32(&h_sm[0][4 * kq]), smem_u32(&h_sm[1][4 * kq]) };

    // ---- per-lane input stream: kq 0/1/2 -> xf/xu/xm for row j; 2-deep ----
    const size_t base = (size_t)b * NS * NM + j;
    const bool active = (kq < 3);
    const float* pxs = (kq == 0) ? (g_xf + base)
                      : (kq == 1) ? (g_xu + base)
                      :             (g_xm + base);
    float v0 = 0.f, v1 = 0.f;
    if (active) { v0 = pxs[0]; v1 = pxs[NM]; }

    // ---- init ----
    h_sm[0][tid] = 0.f;
    if (tid == 0) { MBAR_INIT(smem_u32(&mbar[0]), 8); MBAR_INIT(smem_u32(&mbar[1]), 8); }
    float h_reg = 0.f;
    __syncthreads();
    CLUSTER_SYNC_();   // mbarriers + h_sm[0] visible cluster-wide

    const unsigned FULL = 0xffffffffu;
    const uint32_t mloc[2] = { smem_u32(&mbar[0]), smem_u32(&mbar[1]) };
    int ph0 = 0, ph1 = 0;

    for (int t = 0; t < NS; ++t) {
        const int buf = t & 1;

        // ---- wait for this step's h buffer (8 producer arrivals) ----
        if (t > 0) {
            if (buf) { MBAR_WAIT_CL(mloc[1], ph1); ph1 ^= 1; }
            else     { MBAR_WAIT_CL(mloc[0], ph0); ph0 ^= 1; }
        }

        // ---- dot over interleaved k set, both gates, packed f32x2 ----
        unsigned long long fa = 0ull, fb = 0ull, ua = 0ull, ub = 0ull;
        {
            const uint32_t hb = ha[buf];
            #pragma unroll
            for (int i = 0; i < 8; ++i) {
                unsigned long long h01, h23;
                asm volatile("ld.shared.v2.b64 {%0, %1}, [%2];"
                             : "=l"(h01), "=l"(h23) : "r"(hb + i * 128));
                FFMA2(fa, wf2[2*i+0], h01);
                FFMA2(fb, wf2[2*i+1], h23);
                FFMA2(ua, wu2[2*i+0], h01);
                FFMA2(ub, wu2[2*i+1], h23);
            }
        }
        float f_lo, f_hi, u_lo, u_hi, t_lo, t_hi;
        unpack2(f_lo, f_hi, fa); unpack2(t_lo, t_hi, fb);
        float af = (f_lo + f_hi) + (t_lo + t_hi);
        unpack2(u_lo, u_hi, ua); unpack2(t_lo, t_hi, ub);
        float au = (u_lo + u_hi) + (t_lo + t_hi);

        af += __shfl_xor_sync(FULL, af, 1);
        au += __shfl_xor_sync(FULL, au, 1);
        af += __shfl_xor_sync(FULL, af, 2);
        au += __shfl_xor_sync(FULL, au, 2);
        af += __shfl_xor_sync(FULL, af, 4);
        au += __shfl_xor_sync(FULL, au, 4);

        // ---- broadcast this step's inputs within the row group ----
        const float vc  = buf ? v1 : v0;
        const float xfc = __shfl_sync(FULL, vc, lg + 0);
        const float xuc = __shfl_sync(FULL, vc, lg + 1);
        const float xmc = __shfl_sync(FULL, vc, lg + 2);

        // ---- gates + state update (all 8 lanes redundantly) ----
        const float f = 1.f / (1.f + __expf(-(af + xfc)));
        const float u = 1.f / (1.f + __expf(-(au + xuc)));
        const float hn = fmaf(f, h_reg, u * xmc);
        h_reg = hn;

        // ---- publish next h: one remote store per thread (dest CTA = kq) ----
        if (t + 1 < NS) {
            asm volatile("st.shared::cluster.f32 [%0], %1;"
                         :: "r"(rdst[buf ^ 1]), "f"(hn) : "memory");
        }

        __syncthreads();   // all stores issued + all reads of h_sm[buf] done

        // ---- signal peers: one arrive per peer (threads 0..7) ----
        if (t + 1 < NS && tid < 8) {
            asm volatile("fence.acq_rel.cluster;" ::: "memory");
            asm volatile("mbarrier.arrive.shared::cluster.b64 _, [%0];"
                         :: "r"(rmb[buf ^ 1]) : "memory");
        }

        // ---- overlapped tail: g_H store + t+2 stream refill ----
        if (kq == 0) {
            g_H[(size_t)(b * NS + t) * NM + j] = hn;
            if (t == NS - 1 && hfinal) hfinal[b * NM + j] = hn;
        }
        if (active && t + 2 < NS) {
            const float nv = pxs[(size_t)(t + 2) * NM];
            if (buf) v1 = nv; else v0 = nv;
        }
    }

    CLUSTER_SYNC_();   // no CTA exits while peers may still touch its smem
}

// =====================================================================
extern "C" void kernel_launch(void* const* d_in, const int* in_sizes, int n_in,
                              void* d_out, int out_size)
{
    const float* x  = (const float*)d_in[0];
    const float* Wi = (const float*)d_in[1];
    const float* bi = (const float*)d_in[2];
    const float* Wf = (const float*)d_in[3];
    const float* bf = (const float*)d_in[4];
    const float* Wu = (const float*)d_in[5];
    const float* bu = (const float*)d_in[6];
    const float* Wo = (const float*)d_in[7];
    const float* bo = (const float*)d_in[8];
    float* out = (float*)d_out;

    // Phase 1: xm / xf / xu projections (tf32 tensor cores)
    gemm_kernel<0><<<dim3(NROWS / 128, 6), 256>>>(x, Wi, bi, Wf, bf, Wu, bu, Wo, bo, out);

    // Phase 2: sequential recurrence (16 batches x 8-CTA clusters)
    float* hfinal = nullptr;
    if ((long long)out_size >= (long long)NROWS * ND + (long long)NB * NM)
        hfinal = out + (size_t)NROWS * ND;
    recur_kernel<<<128, 256>>>(Wf, Wu, hfinal);

    // Phase 3: out = x + bo + [X | H] @ Wo^T
    gemm_kernel<1><<<dim3(NROWS / 128, 8), 256>>>(x, Wi, bi, Wf, bf, Wu, bu, Wo, bo, out);
}

// round 9
// speedup vs baseline: 2.1069x; 1.0672x over previous
#include <cuda_runtime.h>
#include <cstdint>
#include <cstddef>

#define NB 16
#define NS 2048
#define ND 1024
#define NM 256
#define NROWS (NB*NS)   // 32768

// ---------------- scratch (device globals: allocation-free) ----------------
__device__ __align__(16) float g_xf[(size_t)NROWS * NM];
__device__ __align__(16) float g_xu[(size_t)NROWS * NM];
__device__ __align__(16) float g_xm[(size_t)NROWS * NM];
__device__ __align__(16) float g_H [(size_t)NROWS * NM];

// ---------------- helpers ----------------
__device__ __forceinline__ uint32_t f2tf32(float x) {
    uint32_t r; asm("cvt.rna.tf32.f32 %0, %1;" : "=r"(r) : "f"(x)); return r;
}
__device__ __forceinline__ void mma_tf32(float c[4], const uint32_t a[4], const uint32_t b[2]) {
    asm volatile("mma.sync.aligned.m16n8k8.row.col.f32.tf32.tf32.f32 "
        "{%0,%1,%2,%3}, {%4,%5,%6,%7}, {%8,%9}, {%0,%1,%2,%3};"
        : "+f"(c[0]), "+f"(c[1]), "+f"(c[2]), "+f"(c[3])
        : "r"(a[0]), "r"(a[1]), "r"(a[2]), "r"(a[3]), "r"(b[0]), "r"(b[1]));
}
__device__ __forceinline__ uint32_t smem_u32(const void* p) {
    return (uint32_t)__cvta_generic_to_shared(p);
}
__device__ __forceinline__ unsigned long long pack2(float lo, float hi) {
    unsigned long long r;
    asm("mov.b64 %0, {%1, %2};" : "=l"(r) : "f"(lo), "f"(hi));
    return r;
}
__device__ __forceinline__ void unpack2(float& lo, float& hi, unsigned long long v) {
    asm("mov.b64 {%0, %1}, %2;" : "=f"(lo), "=f"(hi) : "l"(v));
}
#define FFMA2(acc, a, b) \
    asm("fma.rn.f32x2 %0, %1, %2, %0;" : "+l"(acc) : "l"(a), "l"(b))

#define CLUSTER_SYNC_() do {                                          \
    asm volatile("barrier.cluster.arrive.aligned;" ::: "memory");     \
    asm volatile("barrier.cluster.wait.aligned;"   ::: "memory");     \
} while (0)

#define MBAR_INIT(addr, cnt) \
    asm volatile("mbarrier.init.shared.b64 [%0], %1;" :: "r"(addr), "r"(cnt) : "memory")

// acquire-at-cluster-scope parity wait (architected HW sleep/wake)
#define MBAR_WAIT_CL(addr, par) do {                                         \
    uint32_t _m = (addr); uint32_t _p = (par); uint32_t _done;               \
    asm volatile(                                                            \
        "{\n\t.reg .pred p;\n\t"                                             \
        "mbarrier.try_wait.parity.acquire.cluster.shared::cta.b64 p, [%1], %2;\n\t" \
        "selp.b32 %0, 1, 0, p;\n\t}"                                         \
        : "=r"(_done) : "r"(_m), "r"(_p) : "memory");                        \
    if (!_done) {                                                            \
        asm volatile(                                                        \
            "{\n\t.reg .pred P1;\n\t"                                        \
            "WAIT_LOOP_%=:\n\t"                                              \
            "mbarrier.try_wait.parity.acquire.cluster.shared::cta.b64 P1, [%0], %1, 0x989680;\n\t" \
            "@P1 bra.uni WAIT_DONE_%=;\n\t"                                  \
            "bra.uni WAIT_LOOP_%=;\n\t"                                      \
            "WAIT_DONE_%=:\n\t}"                                             \
            :: "r"(_m), "r"(_p) : "memory");                                 \
    }                                                                        \
} while (0)

// =====================================================================
// GEMM v2: C[row, n] = sum_k A[row, k] * W[n, k]  (tf32 tensor cores)
// BM=128, BN=128, BK=16; 128 threads = 4 warps (2x2); warp tile 64x64.
// Smem re-reads per k-tile: A x2 + B x2 = 32KB (was 48KB with 8 warps).
// MODE 0: N=768 over {Wi, Wf[:, :d], Wu[:, :d]}; +bias, silu for xm
// MODE 1: out = x + bo + [X | H] @ Wo^T
// =====================================================================
template<int MODE>
__global__ void __launch_bounds__(128, 1) gemm_kernel(
    const float* __restrict__ X,
    const float* __restrict__ Wi, const float* __restrict__ bi,
    const float* __restrict__ Wf, const float* __restrict__ bf,
    const float* __restrict__ Wu, const float* __restrict__ bu,
    const float* __restrict__ Wo, const float* __restrict__ bo,
    float* __restrict__ out)
{
    __shared__ uint32_t As[2][128][20];
    __shared__ uint32_t Bs[2][128][20];

    const int tid  = threadIdx.x;
    const int lane = tid & 31;
    const int warp = tid >> 5;    // 0..3
    const int wm   = warp >> 1;   // 0..1
    const int wn   = warp & 1;    // 0..1
    const int bm   = blockIdx.x;
    const int bn   = blockIdx.y;
    const int row0 = bm * 128;
    const int col0 = bn * 128;

    const float* Bmat; int ldb; int K; int nbase;
    const float* bias = bi; float* dst = g_xm; int seg = 0;
    if (MODE == 0) {
        K = 1024;
        seg = bn >> 1;
        Bmat = (seg == 0) ? Wi : ((seg == 1) ? Wf : Wu);
        ldb  = (seg == 0) ? 1024 : 1280;
        nbase = (bn & 1) * 128;
        bias = (seg == 0) ? bi : ((seg == 1) ? bf : bu);
        dst  = (seg == 0) ? g_xm : ((seg == 1) ? g_xf : g_xu);
    } else {
        K = 1280; Bmat = Wo; ldb = 1280; nbase = col0;
    }
    const int NKT = K / 16;

    const int lr = tid >> 2;        // 0..31
    const int lc = (tid & 3) * 4;   // 0,4,8,12

    float acc[4][8][4];
    #pragma unroll
    for (int i = 0; i < 4; i++)
        #pragma unroll
        for (int j = 0; j < 8; j++)
            #pragma unroll
            for (int k = 0; k < 4; k++) acc[i][j][k] = 0.f;

    float4 ra[4], rb[4];

    auto ldgA = [&](int kt) {
        const int kk = kt * 16 + lc;
        #pragma unroll
        for (int h = 0; h < 4; ++h) {
            const int rr = row0 + lr + h * 32;
            if (MODE == 1 && kk >= 1024)
                ra[h] = *(const float4*)(g_H + (size_t)rr * NM + (kk - 1024));
            else
                ra[h] = *(const float4*)(X + (size_t)rr * ND + kk);
        }
    };
    auto ldgB = [&](int kt) {
        const int kk = kt * 16 + lc;
        #pragma unroll
        for (int h = 0; h < 4; ++h) {
            const int rr = nbase + lr + h * 32;
            rb[h] = *(const float4*)(Bmat + (size_t)rr * ldb + kk);
        }
    };
    auto stsAB = [&](int buf) {
        #pragma unroll
        for (int h = 0; h < 4; ++h) {
            uint32_t* pa = &As[buf][lr + h * 32][lc];
            pa[0] = f2tf32(ra[h].x); pa[1] = f2tf32(ra[h].y);
            pa[2] = f2tf32(ra[h].z); pa[3] = f2tf32(ra[h].w);
            uint32_t* pb = &Bs[buf][lr + h * 32][lc];
            pb[0] = f2tf32(rb[h].x); pb[1] = f2tf32(rb[h].y);
            pb[2] = f2tf32(rb[h].z); pb[3] = f2tf32(rb[h].w);
        }
    };
    auto compute = [&](int buf) {
        #pragma unroll
        for (int ks = 0; ks < 2; ++ks) {
            const int k0 = ks * 8 + (lane & 3);
            uint32_t a[4][4]; uint32_t bb[8][2];
            #pragma unroll
            for (int mf = 0; mf < 4; ++mf) {
                const int r = wm * 64 + mf * 16 + (lane >> 2);
                a[mf][0] = As[buf][r    ][k0];
                a[mf][1] = As[buf][r + 8][k0];
                a[mf][2] = As[buf][r    ][k0 + 4];
                a[mf][3] = As[buf][r + 8][k0 + 4];
            }
            #pragma unroll
            for (int nf = 0; nf < 8; ++nf) {
                const int c = wn * 64 + nf * 8 + (lane >> 2);
                bb[nf][0] = Bs[buf][c][k0];
                bb[nf][1] = Bs[buf][c][k0 + 4];
            }
            #pragma unroll
            for (int mf = 0; mf < 4; ++mf)
                #pragma unroll
                for (int nf = 0; nf < 8; ++nf)
                    mma_tf32(acc[mf][nf], a[mf], bb[nf]);
        }
    };

    ldgA(0); ldgB(0);
    stsAB(0);
    __syncthreads();
    for (int kt = 0; kt < NKT; ++kt) {
        const int buf = kt & 1;
        if (kt + 1 < NKT) { ldgA(kt + 1); ldgB(kt + 1); }
        compute(buf);
        if (kt + 1 < NKT) stsAB(buf ^ 1);
        __syncthreads();
    }

    #pragma unroll
    for (int mf = 0; mf < 4; ++mf)
        #pragma unroll
        for (int nf = 0; nf < 8; ++nf)
            #pragma unroll
            for (int h = 0; h < 2; ++h) {
                const int row = row0 + wm * 64 + mf * 16 + (lane >> 2) + h * 8;
                const int c0  = col0 + wn * 64 + nf * 8 + (lane & 3) * 2;
                float v0 = acc[mf][nf][h * 2 + 0];
                float v1 = acc[mf][nf][h * 2 + 1];
                if (MODE == 0) {
                    const int cl = c0 & 255;
                    v0 += bias[cl]; v1 += bias[cl + 1];
                    if (seg == 0) {   // silu for xm
                        v0 = v0 / (1.f + __expf(-v0));
                        v1 = v1 / (1.f + __expf(-v1));
                    }
                    *(float2*)&dst[(size_t)row * NM + cl] = make_float2(v0, v1);
                } else {
                    v0 += bo[c0]     + X[(size_t)row * ND + c0];
                    v1 += bo[c0 + 1] + X[(size_t)row * ND + c0 + 1];
                    *(float2*)&out[(size_t)row * ND + c0] = make_float2(v0, v1);
                }
            }
}

// =====================================================================
// Recurrence v8 = R7 (proven) with the per-step fence.acq_rel.cluster
// removed: the release is folded into the arrive
// (mbarrier.arrive.release.cluster). Ordering chain:
//   remote st (all threads) -> __syncthreads (cta hb-edge) ->
//   arrive.release.cluster (tid<8)  ~sw~  try_wait.acquire.cluster
// PTX happens-before is transitive, so peer h stores are visible after
// the consumer's acquire wait, without the L1-flushing cluster fence.
// =====================================================================
__global__ void __cluster_dims__(8, 1, 1) __launch_bounds__(256)
recur_kernel(const float* __restrict__ Wf, const float* __restrict__ Wu,
             float* __restrict__ hfinal)
{
    const int tid = threadIdx.x;
    const int jj  = tid >> 3;          // local row 0..31
    const int kq  = tid & 7;           // k interleave / dest CTA
    const int r   = blockIdx.x & 7;    // cluster rank (row slice)
    const int b   = blockIdx.x >> 3;
    const int j   = r * 32 + jj;       // global row
    const int lg  = (tid & 31) & ~7;   // row-group leader lane in warp

    __shared__ alignas(16) float h_sm[2][256];
    __shared__ alignas(8) unsigned long long mbar[2];

    // ---- recurrent weights, interleaved k = 32*i + 4*kq + c, packed f32x2 ----
    unsigned long long wf2[16], wu2[16];
    {
        const float* pf = Wf + (size_t)j * 1280 + 1024 + 4 * kq;
        const float* pu = Wu + (size_t)j * 1280 + 1024 + 4 * kq;
        #pragma unroll
        for (int i = 0; i < 8; ++i) {
            float4 vf = *(const float4*)(pf + i * 32);
            float4 vu = *(const float4*)(pu + i * 32);
            wf2[2*i+0] = pack2(vf.x, vf.y);
            wf2[2*i+1] = pack2(vf.z, vf.w);
            wu2[2*i+0] = pack2(vu.x, vu.y);
            wu2[2*i+1] = pack2(vu.z, vu.w);
        }
    }

    // ---- remote h-store addresses: this row's slot in CTA kq, both buffers ----
    uint32_t rdst[2];
    {
        const uint32_t la0 = smem_u32(&h_sm[0][j]);
        const uint32_t la1 = smem_u32(&h_sm[1][j]);
        asm("mapa.shared::cluster.u32 %0, %1, %2;" : "=r"(rdst[0]) : "r"(la0), "r"(kq));
        asm("mapa.shared::cluster.u32 %0, %1, %2;" : "=r"(rdst[1]) : "r"(la1), "r"(kq));
    }

    // ---- remote mbar addresses (tid<8: thread tid arrives on peer tid) ----
    uint32_t rmb[2] = {0u, 0u};
    if (tid < 8) {
        const uint32_t lm0 = smem_u32(&mbar[0]);
        const uint32_t lm1 = smem_u32(&mbar[1]);
        asm("mapa.shared::cluster.u32 %0, %1, %2;" : "=r"(rmb[0]) : "r"(lm0), "r"(tid));
        asm("mapa.shared::cluster.u32 %0, %1, %2;" : "=r"(rmb[1]) : "r"(lm1), "r"(tid));
    }

    // ---- local h read base (both buffers), conflict-free 16B interleave ----
    const uint32_t ha[2] = { smem_u32(&h_sm[0][4 * kq]), smem_u32(&h_sm[1][4 * kq]) };

    // ---- per-lane input stream: kq 0/1/2 -> xf/xu/xm for row j; 2-deep ----
    const size_t base = (size_t)b * NS * NM + j;
    const bool active = (kq < 3);
    const float* pxs = (kq == 0) ? (g_xf + base)
                      : (kq == 1) ? (g_xu + base)
                      :             (g_xm + base);
    float v0 = 0.f, v1 = 0.f;
    if (active) { v0 = pxs[0]; v1 = pxs[NM]; }

    // ---- init ----
    h_sm[0][tid] = 0.f;
    if (tid == 0) { MBAR_INIT(smem_u32(&mbar[0]), 8); MBAR_INIT(smem_u32(&mbar[1]), 8); }
    float h_reg = 0.f;
    __syncthreads();
    CLUSTER_SYNC_();   // mbarriers + h_sm[0] visible cluster-wide

    const unsigned FULL = 0xffffffffu;
    const uint32_t mloc[2] = { smem_u32(&mbar[0]), smem_u32(&mbar[1]) };
    int ph0 = 0, ph1 = 0;

    for (int t = 0; t < NS; ++t) {
        const int buf = t & 1;

        // ---- wait for this step's h buffer (8 producer arrivals) ----
        if (t > 0) {
            if (buf) { MBAR_WAIT_CL(mloc[1], ph1); ph1 ^= 1; }
            else     { MBAR_WAIT_CL(mloc[0], ph0); ph0 ^= 1; }
        }

        // ---- dot over interleaved k set, both gates, packed f32x2 ----
        unsigned long long fa = 0ull, fb = 0ull, ua = 0ull, ub = 0ull;
        {
            const uint32_t hb = ha[buf];
            #pragma unroll
            for (int i = 0; i < 8; ++i) {
                unsigned long long h01, h23;
                asm volatile("ld.shared.v2.b64 {%0, %1}, [%2];"
                             : "=l"(h01), "=l"(h23) : "r"(hb + i * 128));
                FFMA2(fa, wf2[2*i+0], h01);
                FFMA2(fb, wf2[2*i+1], h23);
                FFMA2(ua, wu2[2*i+0], h01);
                FFMA2(ub, wu2[2*i+1], h23);
            }
        }
        float f_lo, f_hi, u_lo, u_hi, t_lo, t_hi;
        unpack2(f_lo, f_hi, fa); unpack2(t_lo, t_hi, fb);
        float af = (f_lo + f_hi) + (t_lo + t_hi);
        unpack2(u_lo, u_hi, ua); unpack2(t_lo, t_hi, ub);
        float au = (u_lo + u_hi) + (t_lo + t_hi);

        af += __shfl_xor_sync(FULL, af, 1);
        au += __shfl_xor_sync(FULL, au, 1);
        af += __shfl_xor_sync(FULL, af, 2);
        au += __shfl_xor_sync(FULL, au, 2);
        af += __shfl_xor_sync(FULL, af, 4);
        au += __shfl_xor_sync(FULL, au, 4);

        // ---- broadcast this step's inputs within the row group ----
        const float vc  = buf ? v1 : v0;
        const float xfc = __shfl_sync(FULL, vc, lg + 0);
        const float xuc = __shfl_sync(FULL, vc, lg + 1);
        const float xmc = __shfl_sync(FULL, vc, lg + 2);

        // ---- gates + state update (all 8 lanes redundantly) ----
        const float f = 1.f / (1.f + __expf(-(af + xfc)));
        const float u = 1.f / (1.f + __expf(-(au + xuc)));
        const float hn = fmaf(f, h_reg, u * xmc);
        h_reg = hn;

        // ---- publish next h: one remote store per thread (dest CTA = kq) ----
        if (t + 1 < NS) {
            asm volatile("st.shared::cluster.f32 [%0], %1;"
                         :: "r"(rdst[buf ^ 1]), "f"(hn) : "memory");
        }

        __syncthreads();   // all stores issued + all reads of h_sm[buf] done

        // ---- signal peers: release folded into the arrive (no fence) ----
        if (t + 1 < NS && tid < 8) {
            asm volatile("mbarrier.arrive.release.cluster.shared::cluster.b64 _, [%0];"
                         :: "r"(rmb[buf ^ 1]) : "memory");
        }

        // ---- overlapped tail: g_H store + t+2 stream refill ----
        if (kq == 0) {
            g_H[(size_t)(b * NS + t) * NM + j] = hn;
            if (t == NS - 1 && hfinal) hfinal[b * NM + j] = hn;
        }
        if (active && t + 2 < NS) {
            const float nv = pxs[(size_t)(t + 2) * NM];
            if (buf) v1 = nv; else v0 = nv;
        }
    }

    CLUSTER_SYNC_();   // no CTA exits while peers may still touch its smem
}

// =====================================================================
extern "C" void kernel_launch(void* const* d_in, const int* in_sizes, int n_in,
                              void* d_out, int out_size)
{
    const float* x  = (const float*)d_in[0];
    const float* Wi = (const float*)d_in[1];
    const float* bi = (const float*)d_in[2];
    const float* Wf = (const float*)d_in[3];
    const float* bf = (const float*)d_in[4];
    const float* Wu = (const float*)d_in[5];
    const float* bu = (const float*)d_in[6];
    const float* Wo = (const float*)d_in[7];
    const float* bo = (const float*)d_in[8];
    float* out = (float*)d_out;

    // Phase 1: xm / xf / xu projections (tf32 tensor cores)
    gemm_kernel<0><<<dim3(NROWS / 128, 6), 128>>>(x, Wi, bi, Wf, bf, Wu, bu, Wo, bo, out);

    // Phase 2: sequential recurrence (16 batches x 8-CTA clusters)
    float* hfinal = nullptr;
    if ((long long)out_size >= (long long)NROWS * ND + (long long)NB * NM)
        hfinal = out + (size_t)NROWS * ND;
    recur_kernel<<<128, 256>>>(Wf, Wu, hfinal);

    // Phase 3: out = x + bo + [X | H] @ Wo^T
    gemm_kernel<1><<<dim3(NROWS / 128, 8), 128>>>(x, Wi, bi, Wf, bf, Wu, bu, Wo, bo, out);
}

// round 10
// speedup vs baseline: 2.2891x; 1.0864x over previous
#include <cuda_runtime.h>
#include <cstdint>
#include <cstddef>

#define NB 16
#define NS 2048
#define ND 1024
#define NM 256
#define NROWS (NB*NS)   // 32768

// ---------------- scratch (device globals: allocation-free) ----------------
__device__ __align__(16) float g_xf[(size_t)NROWS * NM];
__device__ __align__(16) float g_xu[(size_t)NROWS * NM];
__device__ __align__(16) float g_xm[(size_t)NROWS * NM];
__device__ __align__(16) float g_H [(size_t)NROWS * NM];

// ---------------- helpers ----------------
__device__ __forceinline__ uint32_t f2tf32(float x) {
    uint32_t r; asm("cvt.rna.tf32.f32 %0, %1;" : "=r"(r) : "f"(x)); return r;
}
__device__ __forceinline__ void mma_tf32(float c[4], const uint32_t a[4], const uint32_t b[2]) {
    asm volatile("mma.sync.aligned.m16n8k8.row.col.f32.tf32.tf32.f32 "
        "{%0,%1,%2,%3}, {%4,%5,%6,%7}, {%8,%9}, {%0,%1,%2,%3};"
        : "+f"(c[0]), "+f"(c[1]), "+f"(c[2]), "+f"(c[3])
        : "r"(a[0]), "r"(a[1]), "r"(a[2]), "r"(a[3]), "r"(b[0]), "r"(b[1]));
}
__device__ __forceinline__ uint32_t smem_u32(const void* p) {
    return (uint32_t)__cvta_generic_to_shared(p);
}
__device__ __forceinline__ unsigned long long pack2(float lo, float hi) {
    unsigned long long r;
    asm("mov.b64 %0, {%1, %2};" : "=l"(r) : "f"(lo), "f"(hi));
    return r;
}
__device__ __forceinline__ void unpack2(float& lo, float& hi, unsigned long long v) {
    asm("mov.b64 {%0, %1}, %2;" : "=f"(lo), "=f"(hi) : "l"(v));
}
#define FFMA2(acc, a, b) \
    asm("fma.rn.f32x2 %0, %1, %2, %0;" : "+l"(acc) : "l"(a), "l"(b))

#define CLUSTER_SYNC_() do {                                          \
    asm volatile("barrier.cluster.arrive.aligned;" ::: "memory");     \
    asm volatile("barrier.cluster.wait.aligned;"   ::: "memory");     \
} while (0)

#define MBAR_INIT(addr, cnt) \
    asm volatile("mbarrier.init.shared.b64 [%0], %1;" :: "r"(addr), "r"(cnt) : "memory")

#define MBAR_WAIT_CL(addr, par) do {                                         \
    uint32_t _m = (addr); uint32_t _p = (par); uint32_t _done;               \
    asm volatile(                                                            \
        "{\n\t.reg .pred p;\n\t"                                             \
        "mbarrier.try_wait.parity.acquire.cluster.shared::cta.b64 p, [%1], %2;\n\t" \
        "selp.b32 %0, 1, 0, p;\n\t}"                                         \
        : "=r"(_done) : "r"(_m), "r"(_p) : "memory");                        \
    if (!_done) {                                                            \
        asm volatile(                                                        \
            "{\n\t.reg .pred P1;\n\t"                                        \
            "WAIT_LOOP_%=:\n\t"                                              \
            "mbarrier.try_wait.parity.acquire.cluster.shared::cta.b64 P1, [%0], %1, 0x989680;\n\t" \
            "@P1 bra.uni WAIT_DONE_%=;\n\t"                                  \
            "bra.uni WAIT_LOOP_%=;\n\t"                                      \
            "WAIT_DONE_%=:\n\t}"                                             \
            :: "r"(_m), "r"(_p) : "memory");                                 \
    }                                                                        \
} while (0)

// =====================================================================
// GEMM (projections): 128 threads, 4 warps (2x2), warp tile 64x64.
// C = X @ W^T (+bias, silu for xm) -> g_xm / g_xf / g_xu. K=1024.
// (R8's proven 4-warp kernel, MODE 0 only.)
// =====================================================================
__global__ void __launch_bounds__(128, 1) gemm_proj_kernel(
    const float* __restrict__ X,
    const float* __restrict__ Wi, const float* __restrict__ bi,
    const float* __restrict__ Wf, const float* __restrict__ bf,
    const float* __restrict__ Wu, const float* __restrict__ bu)
{
    __shared__ uint32_t As[2][128][20];
    __shared__ uint32_t Bs[2][128][20];

    const int tid  = threadIdx.x;
    const int lane = tid & 31;
    const int warp = tid >> 5;
    const int wm   = warp >> 1;
    const int wn   = warp & 1;
    const int row0 = blockIdx.x * 128;
    const int bn   = blockIdx.y;

    const int seg = bn >> 1;
    const float* Bmat = (seg == 0) ? Wi : ((seg == 1) ? Wf : Wu);
    const int ldb     = (seg == 0) ? 1024 : 1280;
    const int nbase   = (bn & 1) * 128;
    const float* bias = (seg == 0) ? bi : ((seg == 1) ? bf : bu);
    float* dst        = (seg == 0) ? g_xm : ((seg == 1) ? g_xf : g_xu);
    const int NKT = 1024 / 16;

    const int lr = tid >> 2;
    const int lc = (tid & 3) * 4;

    float acc[4][8][4];
    #pragma unroll
    for (int i = 0; i < 4; i++)
        #pragma unroll
        for (int j = 0; j < 8; j++)
            #pragma unroll
            for (int k = 0; k < 4; k++) acc[i][j][k] = 0.f;

    float4 ra[4], rb[4];
    auto ldgA = [&](int kt) {
        const int kk = kt * 16 + lc;
        #pragma unroll
        for (int h = 0; h < 4; ++h)
            ra[h] = *(const float4*)(X + (size_t)(row0 + lr + h * 32) * ND + kk);
    };
    auto ldgB = [&](int kt) {
        const int kk = kt * 16 + lc;
        #pragma unroll
        for (int h = 0; h < 4; ++h)
            rb[h] = *(const float4*)(Bmat + (size_t)(nbase + lr + h * 32) * ldb + kk);
    };
    auto stsAB = [&](int buf) {
        #pragma unroll
        for (int h = 0; h < 4; ++h) {
            uint32_t* pa = &As[buf][lr + h * 32][lc];
            pa[0] = f2tf32(ra[h].x); pa[1] = f2tf32(ra[h].y);
            pa[2] = f2tf32(ra[h].z); pa[3] = f2tf32(ra[h].w);
            uint32_t* pb = &Bs[buf][lr + h * 32][lc];
            pb[0] = f2tf32(rb[h].x); pb[1] = f2tf32(rb[h].y);
            pb[2] = f2tf32(rb[h].z); pb[3] = f2tf32(rb[h].w);
        }
    };
    auto compute = [&](int buf) {
        #pragma unroll
        for (int ks = 0; ks < 2; ++ks) {
            const int k0 = ks * 8 + (lane & 3);
            uint32_t a[4][4]; uint32_t bb[8][2];
            #pragma unroll
            for (int mf = 0; mf < 4; ++mf) {
                const int r = wm * 64 + mf * 16 + (lane >> 2);
                a[mf][0] = As[buf][r    ][k0];
                a[mf][1] = As[buf][r + 8][k0];
                a[mf][2] = As[buf][r    ][k0 + 4];
                a[mf][3] = As[buf][r + 8][k0 + 4];
            }
            #pragma unroll
            for (int nf = 0; nf < 8; ++nf) {
                const int c = wn * 64 + nf * 8 + (lane >> 2);
                bb[nf][0] = Bs[buf][c][k0];
                bb[nf][1] = Bs[buf][c][k0 + 4];
            }
            #pragma unroll
            for (int mf = 0; mf < 4; ++mf)
                #pragma unroll
                for (int nf = 0; nf < 8; ++nf)
                    mma_tf32(acc[mf][nf], a[mf], bb[nf]);
        }
    };

    ldgA(0); ldgB(0); stsAB(0);
    __syncthreads();
    for (int kt = 0; kt < NKT; ++kt) {
        const int buf = kt & 1;
        if (kt + 1 < NKT) { ldgA(kt + 1); ldgB(kt + 1); }
        compute(buf);
        if (kt + 1 < NKT) stsAB(buf ^ 1);
        __syncthreads();
    }

    #pragma unroll
    for (int mf = 0; mf < 4; ++mf)
        #pragma unroll
        for (int nf = 0; nf < 8; ++nf)
            #pragma unroll
            for (int h = 0; h < 2; ++h) {
                const int row = row0 + wm * 64 + mf * 16 + (lane >> 2) + h * 8;
                const int cl  = (wn * 64 + nf * 8 + (lane & 3) * 2) + nbase - ((bn & 1) * 128);
                const int c   = wn * 64 + nf * 8 + (lane & 3) * 2;   // 0..127
                const int cc  = ((bn & 1) * 128 + c) & 255;
                float v0 = acc[mf][nf][h * 2 + 0] + bias[cc];
                float v1 = acc[mf][nf][h * 2 + 1] + bias[cc + 1];
                (void)cl;
                if (seg == 0) {
                    v0 = v0 / (1.f + __expf(-v0));
                    v1 = v1 / (1.f + __expf(-v1));
                }
                *(float2*)&dst[(size_t)row * NM + cc] = make_float2(v0, v1);
            }
}

// =====================================================================
// FUSED kernel: blocks [0,128) = recurrence clusters (R8's proven v8),
// blocks [128, 128+2048) = gemm1a tiles: out = x + bo + X @ Wo[:, :1024]^T
// (8-warp R1-style gemm, 256 threads). The gemm work co-resides with the
// latency-bound recurrence and is hidden behind it.
// =====================================================================
#define GEMM1A_BLOCKS 2048

__global__ void __cluster_dims__(8, 1, 1) __launch_bounds__(256, 2)
fused_recur_gemm_kernel(
    const float* __restrict__ X,
    const float* __restrict__ Wf, const float* __restrict__ Wu,
    const float* __restrict__ Wo, const float* __restrict__ bo,
    float* __restrict__ hfinal, float* __restrict__ out)
{
    __shared__ uint32_t As[2][128][20];
    __shared__ uint32_t Bs[2][128][20];
    __shared__ alignas(16) float h_sm[2][256];
    __shared__ alignas(8) unsigned long long mbar[2];

    const int tid = threadIdx.x;

    if (blockIdx.x < 128) {
        // ================= recurrence path (identical to R8) =================
        const int jj  = tid >> 3;
        const int kq  = tid & 7;
        const int r   = blockIdx.x & 7;
        const int b   = blockIdx.x >> 3;
        const int j   = r * 32 + jj;
        const int lg  = (tid & 31) & ~7;

        unsigned long long wf2[16], wu2[16];
        {
            const float* pf = Wf + (size_t)j * 1280 + 1024 + 4 * kq;
            const float* pu = Wu + (size_t)j * 1280 + 1024 + 4 * kq;
            #pragma unroll
            for (int i = 0; i < 8; ++i) {
                float4 vf = *(const float4*)(pf + i * 32);
                float4 vu = *(const float4*)(pu + i * 32);
                wf2[2*i+0] = pack2(vf.x, vf.y);
                wf2[2*i+1] = pack2(vf.z, vf.w);
                wu2[2*i+0] = pack2(vu.x, vu.y);
                wu2[2*i+1] = pack2(vu.z, vu.w);
            }
        }

        uint32_t rdst[2];
        {
            const uint32_t la0 = smem_u32(&h_sm[0][j]);
            const uint32_t la1 = smem_u32(&h_sm[1][j]);
            asm("mapa.shared::cluster.u32 %0, %1, %2;" : "=r"(rdst[0]) : "r"(la0), "r"(kq));
            asm("mapa.shared::cluster.u32 %0, %1, %2;" : "=r"(rdst[1]) : "r"(la1), "r"(kq));
        }
        uint32_t rmb[2] = {0u, 0u};
        if (tid < 8) {
            const uint32_t lm0 = smem_u32(&mbar[0]);
            const uint32_t lm1 = smem_u32(&mbar[1]);
            asm("mapa.shared::cluster.u32 %0, %1, %2;" : "=r"(rmb[0]) : "r"(lm0), "r"(tid));
            asm("mapa.shared::cluster.u32 %0, %1, %2;" : "=r"(rmb[1]) : "r"(lm1), "r"(tid));
        }
        const uint32_t ha[2] = { smem_u32(&h_sm[0][4 * kq]), smem_u32(&h_sm[1][4 * kq]) };

        const size_t base = (size_t)b * NS * NM + j;
        const bool active = (kq < 3);
        const float* pxs = (kq == 0) ? (g_xf + base)
                          : (kq == 1) ? (g_xu + base)
                          :             (g_xm + base);
        float v0 = 0.f, v1 = 0.f;
        if (active) { v0 = pxs[0]; v1 = pxs[NM]; }

        h_sm[0][tid] = 0.f;
        if (tid == 0) { MBAR_INIT(smem_u32(&mbar[0]), 8); MBAR_INIT(smem_u32(&mbar[1]), 8); }
        float h_reg = 0.f;
        __syncthreads();
        CLUSTER_SYNC_();

        const unsigned FULL = 0xffffffffu;
        const uint32_t mloc[2] = { smem_u32(&mbar[0]), smem_u32(&mbar[1]) };
        int ph0 = 0, ph1 = 0;

        for (int t = 0; t < NS; ++t) {
            const int buf = t & 1;

            if (t > 0) {
                if (buf) { MBAR_WAIT_CL(mloc[1], ph1); ph1 ^= 1; }
                else     { MBAR_WAIT_CL(mloc[0], ph0); ph0 ^= 1; }
            }

            unsigned long long fa = 0ull, fb = 0ull, ua = 0ull, ub = 0ull;
            {
                const uint32_t hb = ha[buf];
                #pragma unroll
                for (int i = 0; i < 8; ++i) {
                    unsigned long long h01, h23;
                    asm volatile("ld.shared.v2.b64 {%0, %1}, [%2];"
                                 : "=l"(h01), "=l"(h23) : "r"(hb + i * 128));
                    FFMA2(fa, wf2[2*i+0], h01);
                    FFMA2(fb, wf2[2*i+1], h23);
                    FFMA2(ua, wu2[2*i+0], h01);
                    FFMA2(ub, wu2[2*i+1], h23);
                }
            }
            float f_lo, f_hi, u_lo, u_hi, t_lo, t_hi;
            unpack2(f_lo, f_hi, fa); unpack2(t_lo, t_hi, fb);
            float af = (f_lo + f_hi) + (t_lo + t_hi);
            unpack2(u_lo, u_hi, ua); unpack2(t_lo, t_hi, ub);
            float au = (u_lo + u_hi) + (t_lo + t_hi);

            af += __shfl_xor_sync(FULL, af, 1);
            au += __shfl_xor_sync(FULL, au, 1);
            af += __shfl_xor_sync(FULL, af, 2);
            au += __shfl_xor_sync(FULL, au, 2);
            af += __shfl_xor_sync(FULL, af, 4);
            au += __shfl_xor_sync(FULL, au, 4);

            const float vc  = buf ? v1 : v0;
            const float xfc = __shfl_sync(FULL, vc, lg + 0);
            const float xuc = __shfl_sync(FULL, vc, lg + 1);
            const float xmc = __shfl_sync(FULL, vc, lg + 2);

            const float f = 1.f / (1.f + __expf(-(af + xfc)));
            const float u = 1.f / (1.f + __expf(-(au + xuc)));
            const float hn = fmaf(f, h_reg, u * xmc);
            h_reg = hn;

            if (t + 1 < NS) {
                asm volatile("st.shared::cluster.f32 [%0], %1;"
                             :: "r"(rdst[buf ^ 1]), "f"(hn) : "memory");
            }

            __syncthreads();

            if (t + 1 < NS && tid < 8) {
                asm volatile("mbarrier.arrive.release.cluster.shared::cluster.b64 _, [%0];"
                             :: "r"(rmb[buf ^ 1]) : "memory");
            }

            if (kq == 0) {
                g_H[(size_t)(b * NS + t) * NM + j] = hn;
                if (t == NS - 1 && hfinal) hfinal[b * NM + j] = hn;
            }
            if (active && t + 2 < NS) {
                const float nv = pxs[(size_t)(t + 2) * NM];
                if (buf) v1 = nv; else v0 = nv;
            }
        }

        CLUSTER_SYNC_();
        return;
    }

    // ================= gemm1a path: out = x + bo + X @ Wo[:, :1024]^T ========
    // 256 threads, 8 warps (4x2), warp tile 32x64 (R1's proven config)
    {
        const int gid  = blockIdx.x - 128;
        const int bm   = gid >> 3;          // 0..255
        const int bn   = gid & 7;           // 0..7
        const int row0 = bm * 128;
        const int col0 = bn * 128;
        const int lane = tid & 31;
        const int warp = tid >> 5;
        const int wm   = warp >> 1;         // 0..3
        const int wn   = warp & 1;          // 0..1
        const int NKT  = 1024 / 16;

        const int lr = tid >> 2;            // 0..63
        const int lc = (tid & 3) * 4;

        float acc[2][8][4];
        #pragma unroll
        for (int i = 0; i < 2; i++)
            #pragma unroll
            for (int j = 0; j < 8; j++)
                #pragma unroll
                for (int k = 0; k < 4; k++) acc[i][j][k] = 0.f;

        float4 ra[2], rb[2];
        auto ldgA = [&](int kt) {
            const int kk = kt * 16 + lc;
            #pragma unroll
            for (int h = 0; h < 2; ++h)
                ra[h] = *(const float4*)(X + (size_t)(row0 + lr + h * 64) * ND + kk);
        };
        auto ldgB = [&](int kt) {
            const int kk = kt * 16 + lc;
            #pragma unroll
            for (int h = 0; h < 2; ++h)
                rb[h] = *(const float4*)(Wo + (size_t)(col0 + lr + h * 64) * 1280 + kk);
        };
        auto stsAB = [&](int buf) {
            #pragma unroll
            for (int h = 0; h < 2; ++h) {
                uint32_t* pa = &As[buf][lr + h * 64][lc];
                pa[0] = f2tf32(ra[h].x); pa[1] = f2tf32(ra[h].y);
                pa[2] = f2tf32(ra[h].z); pa[3] = f2tf32(ra[h].w);
                uint32_t* pb = &Bs[buf][lr + h * 64][lc];
                pb[0] = f2tf32(rb[h].x); pb[1] = f2tf32(rb[h].y);
                pb[2] = f2tf32(rb[h].z); pb[3] = f2tf32(rb[h].w);
            }
        };
        auto compute = [&](int buf) {
            #pragma unroll
            for (int ks = 0; ks < 2; ++ks) {
                const int k0 = ks * 8 + (lane & 3);
                uint32_t a[2][4]; uint32_t bb[8][2];
                #pragma unroll
                for (int mf = 0; mf < 2; ++mf) {
                    const int r = wm * 32 + mf * 16 + (lane >> 2);
                    a[mf][0] = As[buf][r    ][k0];
                    a[mf][1] = As[buf][r + 8][k0];
                    a[mf][2] = As[buf][r    ][k0 + 4];
                    a[mf][3] = As[buf][r + 8][k0 + 4];
                }
                #pragma unroll
                for (int nf = 0; nf < 8; ++nf) {
                    const int c = wn * 64 + nf * 8 + (lane >> 2);
                    bb[nf][0] = Bs[buf][c][k0];
                    bb[nf][1] = Bs[buf][c][k0 + 4];
                }
                #pragma unroll
                for (int mf = 0; mf < 2; ++mf)
                    #pragma unroll
                    for (int nf = 0; nf < 8; ++nf)
                        mma_tf32(acc[mf][nf], a[mf], bb[nf]);
            }
        };

        ldgA(0); ldgB(0); stsAB(0);
        __syncthreads();
        for (int kt = 0; kt < NKT; ++kt) {
            const int buf = kt & 1;
            if (kt + 1 < NKT) { ldgA(kt + 1); ldgB(kt + 1); }
            compute(buf);
            if (kt + 1 < NKT) stsAB(buf ^ 1);
            __syncthreads();
        }

        #pragma unroll
        for (int mf = 0; mf < 2; ++mf)
            #pragma unroll
            for (int nf = 0; nf < 8; ++nf)
                #pragma unroll
                for (int h = 0; h < 2; ++h) {
                    const int row = row0 + wm * 32 + mf * 16 + (lane >> 2) + h * 8;
                    const int c0  = col0 + wn * 64 + nf * 8 + (lane & 3) * 2;
                    float v0 = acc[mf][nf][h * 2 + 0] + bo[c0]     + X[(size_t)row * ND + c0];
                    float v1 = acc[mf][nf][h * 2 + 1] + bo[c0 + 1] + X[(size_t)row * ND + c0 + 1];
                    *(float2*)&out[(size_t)row * ND + c0] = make_float2(v0, v1);
                }
    }
}

// =====================================================================
// gemm1b: out += H @ Wo[:, 1024:1280]^T   (K=256, accumulate)
// 128 threads, 4 warps, warp tile 64x64.
// =====================================================================
__global__ void __launch_bounds__(128, 1) gemm_h_kernel(
    const float* __restrict__ Wo, float* __restrict__ out)
{
    __shared__ uint32_t As[2][128][20];
    __shared__ uint32_t Bs[2][128][20];

    const int tid  = threadIdx.x;
    const int lane = tid & 31;
    const int warp = tid >> 5;
    const int wm   = warp >> 1;
    const int wn   = warp & 1;
    const int row0 = blockIdx.x * 128;
    const int col0 = blockIdx.y * 128;
    const int NKT  = 256 / 16;

    const int lr = tid >> 2;
    const int lc = (tid & 3) * 4;

    float acc[4][8][4];
    #pragma unroll
    for (int i = 0; i < 4; i++)
        #pragma unroll
        for (int j = 0; j < 8; j++)
            #pragma unroll
            for (int k = 0; k < 4; k++) acc[i][j][k] = 0.f;

    float4 ra[4], rb[4];
    auto ldgA = [&](int kt) {
        const int kk = kt * 16 + lc;
        #pragma unroll
        for (int h = 0; h < 4; ++h)
            ra[h] = *(const float4*)(g_H + (size_t)(row0 + lr + h * 32) * NM + kk);
    };
    auto ldgB = [&](int kt) {
        const int kk = kt * 16 + lc;
        #pragma unroll
        for (int h = 0; h < 4; ++h)
            rb[h] = *(const float4*)(Wo + (size_t)(col0 + lr + h * 32) * 1280 + 1024 + kk);
    };
    auto stsAB = [&](int buf) {
        #pragma unroll
        for (int h = 0; h < 4; ++h) {
            uint32_t* pa = &As[buf][lr + h * 32][lc];
            pa[0] = f2tf32(ra[h].x); pa[1] = f2tf32(ra[h].y);
            pa[2] = f2tf32(ra[h].z); pa[3] = f2tf32(ra[h].w);
            uint32_t* pb = &Bs[buf][lr + h * 32][lc];
            pb[0] = f2tf32(rb[h].x); pb[1] = f2tf32(rb[h].y);
            pb[2] = f2tf32(rb[h].z); pb[3] = f2tf32(rb[h].w);
        }
    };
    auto compute = [&](int buf) {
        #pragma unroll
        for (int ks = 0; ks < 2; ++ks) {
            const int k0 = ks * 8 + (lane & 3);
            uint32_t a[4][4]; uint32_t bb[8][2];
            #pragma unroll
            for (int mf = 0; mf < 4; ++mf) {
                const int r = wm * 64 + mf * 16 + (lane >> 2);
                a[mf][0] = As[buf][r    ][k0];
                a[mf][1] = As[buf][r + 8][k0];
                a[mf][2] = As[buf][r    ][k0 + 4];
                a[mf][3] = As[buf][r + 8][k0 + 4];
            }
            #pragma unroll
            for (int nf = 0; nf < 8; ++nf) {
                const int c = wn * 64 + nf * 8 + (lane >> 2);
                bb[nf][0] = Bs[buf][c][k0];
                bb[nf][1] = Bs[buf][c][k0 + 4];
            }
            #pragma unroll
            for (int mf = 0; mf < 4; ++mf)
                #pragma unroll
                for (int nf = 0; nf < 8; ++nf)
                    mma_tf32(acc[mf][nf], a[mf], bb[nf]);
        }
    };

    ldgA(0); ldgB(0); stsAB(0);
    __syncthreads();
    for (int kt = 0; kt < NKT; ++kt) {
        const int buf = kt & 1;
        if (kt + 1 < NKT) { ldgA(kt + 1); ldgB(kt + 1); }
        compute(buf);
        if (kt + 1 < NKT) stsAB(buf ^ 1);
        __syncthreads();
    }

    #pragma unroll
    for (int mf = 0; mf < 4; ++mf)
        #pragma unroll
        for (int nf = 0; nf < 8; ++nf)
            #pragma unroll
            for (int h = 0; h < 2; ++h) {
                const int row = row0 + wm * 64 + mf * 16 + (lane >> 2) + h * 8;
                const int c0  = col0 + wn * 64 + nf * 8 + (lane & 3) * 2;
                float2 cur = *(float2*)&out[(size_t)row * ND + c0];
                cur.x += acc[mf][nf][h * 2 + 0];
                cur.y += acc[mf][nf][h * 2 + 1];
                *(float2*)&out[(size_t)row * ND + c0] = cur;
            }
}

// =====================================================================
extern "C" void kernel_launch(void* const* d_in, const int* in_sizes, int n_in,
                              void* d_out, int out_size)
{
    const float* x  = (const float*)d_in[0];
    const float* Wi = (const float*)d_in[1];
    const float* bi = (const float*)d_in[2];
    const float* Wf = (const float*)d_in[3];
    const float* bf = (const float*)d_in[4];
    const float* Wu = (const float*)d_in[5];
    const float* bu = (const float*)d_in[6];
    const float* Wo = (const float*)d_in[7];
    const float* bo = (const float*)d_in[8];
    float* out = (float*)d_out;

    // Phase 1: xm / xf / xu projections (tf32 tensor cores)
    gemm_proj_kernel<<<dim3(NROWS / 128, 6), 128>>>(x, Wi, bi, Wf, bf, Wu, bu);

    // Phase 2: recurrence (blocks 0..127) + hidden gemm1a (blocks 128..2175)
    float* hfinal = nullptr;
    if ((long long)out_size >= (long long)NROWS * ND + (long long)NB * NM)
        hfinal = out + (size_t)NROWS * ND;
    fused_recur_gemm_kernel<<<128 + GEMM1A_BLOCKS, 256>>>(x, Wf, Wu, Wo, bo, hfinal, out);

    // Phase 3: out += H @ Wo[:, 1024:]^T  (K=256)
    gemm_h_kernel<<<dim3(NROWS / 128, 8), 128>>>(Wo, out);
}

// round 11
// speedup vs baseline: 2.4110x; 1.0533x over previous
#include <cuda_runtime.h>
#include <cstdint>
#include <cstddef>

#define NB 16
#define NS 2048
#define ND 1024
#define NM 256
#define NROWS (NB*NS)   // 32768

// ---------------- scratch (device globals: allocation-free) ----------------
__device__ __align__(16) float g_xf[(size_t)NROWS * NM];
__device__ __align__(16) float g_xu[(size_t)NROWS * NM];
__device__ __align__(16) float g_xm[(size_t)NROWS * NM];
__device__ __align__(16) float g_H [(size_t)NROWS * NM];
__device__ int g_prog[256];   // per row-block (b*16+chunk) proj-tile counter (0..6)

// ---------------- helpers ----------------
__device__ __forceinline__ uint32_t f2tf32(float x) {
    uint32_t r; asm("cvt.rna.tf32.f32 %0, %1;" : "=r"(r) : "f"(x)); return r;
}
__device__ __forceinline__ void mma_tf32(float c[4], const uint32_t a[4], const uint32_t b[2]) {
    asm volatile("mma.sync.aligned.m16n8k8.row.col.f32.tf32.tf32.f32 "
        "{%0,%1,%2,%3}, {%4,%5,%6,%7}, {%8,%9}, {%0,%1,%2,%3};"
        : "+f"(c[0]), "+f"(c[1]), "+f"(c[2]), "+f"(c[3])
        : "r"(a[0]), "r"(a[1]), "r"(a[2]), "r"(a[3]), "r"(b[0]), "r"(b[1]));
}
__device__ __forceinline__ uint32_t smem_u32(const void* p) {
    return (uint32_t)__cvta_generic_to_shared(p);
}
__device__ __forceinline__ unsigned long long pack2(float lo, float hi) {
    unsigned long long r;
    asm("mov.b64 %0, {%1, %2};" : "=l"(r) : "f"(lo), "f"(hi));
    return r;
}
__device__ __forceinline__ void unpack2(float& lo, float& hi, unsigned long long v) {
    asm("mov.b64 {%0, %1}, %2;" : "=f"(lo), "=f"(hi) : "l"(v));
}
#define FFMA2(acc, a, b) \
    asm("fma.rn.f32x2 %0, %1, %2, %0;" : "+l"(acc) : "l"(a), "l"(b))

#define CLUSTER_SYNC_() do {                                          \
    asm volatile("barrier.cluster.arrive.aligned;" ::: "memory");     \
    asm volatile("barrier.cluster.wait.aligned;"   ::: "memory");     \
} while (0)

#define MBAR_INIT(addr, cnt) \
    asm volatile("mbarrier.init.shared.b64 [%0], %1;" :: "r"(addr), "r"(cnt) : "memory")

#define MBAR_WAIT_CL(addr, par) do {                                         \
    uint32_t _m = (addr); uint32_t _p = (par); uint32_t _done;               \
    asm volatile(                                                            \
        "{\n\t.reg .pred p;\n\t"                                             \
        "mbarrier.try_wait.parity.acquire.cluster.shared::cta.b64 p, [%1], %2;\n\t" \
        "selp.b32 %0, 1, 0, p;\n\t}"                                         \
        : "=r"(_done) : "r"(_m), "r"(_p) : "memory");                        \
    if (!_done) {                                                            \
        asm volatile(                                                        \
            "{\n\t.reg .pred P1;\n\t"                                        \
            "WAIT_LOOP_%=:\n\t"                                              \
            "mbarrier.try_wait.parity.acquire.cluster.shared::cta.b64 P1, [%0], %1, 0x989680;\n\t" \
            "@P1 bra.uni WAIT_DONE_%=;\n\t"                                  \
            "bra.uni WAIT_LOOP_%=;\n\t"                                      \
            "WAIT_DONE_%=:\n\t}"                                             \
            :: "r"(_m), "r"(_p) : "memory");                                 \
    }                                                                        \
} while (0)

// spin until g_prog[idx] == 6 (acquire: proj stores then visible)
__device__ __forceinline__ void wait_chunk(const int* cptr) {
    int v;
    while (true) {
        asm volatile("ld.global.acquire.gpu.b32 %0, [%1];" : "=r"(v) : "l"(cptr));
        if (v >= 6) break;
        __nanosleep(64);
    }
}

// =====================================================================
// clear progress counters (graph replays must start from zero)
// =====================================================================
__global__ void clear_prog_kernel() { g_prog[threadIdx.x] = 0; }

// =====================================================================
// MEGAKERNEL. Block roles by blockIdx.x:
//   [0, 128)            recurrence: 16 clusters x 8 CTAs (R8 core),
//                       gated per 128-step chunk on g_prog
//   [128, 128+1536)     proj tiles: {xm|xf|xu} = act(X @ W^T + b),
//                       chunk-major order; each tile bumps g_prog
//   [1664, 1664+2048)   gemm1a tiles: out = x + bo + X @ Wo[:, :1024]^T
// =====================================================================
#define PROJ_BLOCKS  1536
#define GEMM1A_BLOCKS 2048

__global__ void __cluster_dims__(8, 1, 1) __launch_bounds__(256, 2)
megakernel(
    const float* __restrict__ X,
    const float* __restrict__ Wi, const float* __restrict__ bi,
    const float* __restrict__ Wf, const float* __restrict__ bf,
    const float* __restrict__ Wu, const float* __restrict__ bu,
    const float* __restrict__ Wo, const float* __restrict__ bo,
    float* __restrict__ hfinal, float* __restrict__ out)
{
    __shared__ uint32_t As[2][128][20];
    __shared__ uint32_t Bs[2][128][20];
    __shared__ alignas(16) float h_sm[2][256];
    __shared__ alignas(8) unsigned long long mbar[2];

    const int tid = threadIdx.x;

    if (blockIdx.x < 128) {
        // ================= recurrence path (R8 core + chunk gating) ==========
        const int jj  = tid >> 3;
        const int kq  = tid & 7;
        const int r   = blockIdx.x & 7;
        const int b   = blockIdx.x >> 3;
        const int j   = r * 32 + jj;
        const int lg  = (tid & 31) & ~7;

        unsigned long long wf2[16], wu2[16];
        {
            const float* pf = Wf + (size_t)j * 1280 + 1024 + 4 * kq;
            const float* pu = Wu + (size_t)j * 1280 + 1024 + 4 * kq;
            #pragma unroll
            for (int i = 0; i < 8; ++i) {
                float4 vf = *(const float4*)(pf + i * 32);
                float4 vu = *(const float4*)(pu + i * 32);
                wf2[2*i+0] = pack2(vf.x, vf.y);
                wf2[2*i+1] = pack2(vf.z, vf.w);
                wu2[2*i+0] = pack2(vu.x, vu.y);
                wu2[2*i+1] = pack2(vu.z, vu.w);
            }
        }

        uint32_t rdst[2];
        {
            const uint32_t la0 = smem_u32(&h_sm[0][j]);
            const uint32_t la1 = smem_u32(&h_sm[1][j]);
            asm("mapa.shared::cluster.u32 %0, %1, %2;" : "=r"(rdst[0]) : "r"(la0), "r"(kq));
            asm("mapa.shared::cluster.u32 %0, %1, %2;" : "=r"(rdst[1]) : "r"(la1), "r"(kq));
        }
        uint32_t rmb[2] = {0u, 0u};
        if (tid < 8) {
            const uint32_t lm0 = smem_u32(&mbar[0]);
            const uint32_t lm1 = smem_u32(&mbar[1]);
            asm("mapa.shared::cluster.u32 %0, %1, %2;" : "=r"(rmb[0]) : "r"(lm0), "r"(tid));
            asm("mapa.shared::cluster.u32 %0, %1, %2;" : "=r"(rmb[1]) : "r"(lm1), "r"(tid));
        }
        const uint32_t ha[2] = { smem_u32(&h_sm[0][4 * kq]), smem_u32(&h_sm[1][4 * kq]) };

        const size_t base = (size_t)b * NS * NM + j;
        const bool active = (kq < 3);
        const float* pxs = (kq == 0) ? (g_xf + base)
                          : (kq == 1) ? (g_xu + base)
                          :             (g_xm + base);

        h_sm[0][tid] = 0.f;
        if (tid == 0) { MBAR_INIT(smem_u32(&mbar[0]), 8); MBAR_INIT(smem_u32(&mbar[1]), 8); }
        float h_reg = 0.f;
        __syncthreads();
        CLUSTER_SYNC_();

        // gate on chunk 0 of this batch, then do initial 2-deep prefetch
        wait_chunk(&g_prog[b * 16]);
        float v0 = 0.f, v1 = 0.f;
        if (active) { v0 = pxs[0]; v1 = pxs[NM]; }

        const unsigned FULL = 0xffffffffu;
        const uint32_t mloc[2] = { smem_u32(&mbar[0]), smem_u32(&mbar[1]) };
        int ph0 = 0, ph1 = 0;

        for (int t = 0; t < NS; ++t) {
            const int buf = t & 1;

            if (t > 0) {
                if (buf) { MBAR_WAIT_CL(mloc[1], ph1); ph1 ^= 1; }
                else     { MBAR_WAIT_CL(mloc[0], ph0); ph0 ^= 1; }
            }

            unsigned long long fa = 0ull, fb = 0ull, ua = 0ull, ub = 0ull;
            {
                const uint32_t hb = ha[buf];
                #pragma unroll
                for (int i = 0; i < 8; ++i) {
                    unsigned long long h01, h23;
                    asm volatile("ld.shared.v2.b64 {%0, %1}, [%2];"
                                 : "=l"(h01), "=l"(h23) : "r"(hb + i * 128));
                    FFMA2(fa, wf2[2*i+0], h01);
                    FFMA2(fb, wf2[2*i+1], h23);
                    FFMA2(ua, wu2[2*i+0], h01);
                    FFMA2(ub, wu2[2*i+1], h23);
                }
            }
            float f_lo, f_hi, u_lo, u_hi, t_lo, t_hi;
            unpack2(f_lo, f_hi, fa); unpack2(t_lo, t_hi, fb);
            float af = (f_lo + f_hi) + (t_lo + t_hi);
            unpack2(u_lo, u_hi, ua); unpack2(t_lo, t_hi, ub);
            float au = (u_lo + u_hi) + (t_lo + t_hi);

            af += __shfl_xor_sync(FULL, af, 1);
            au += __shfl_xor_sync(FULL, au, 1);
            af += __shfl_xor_sync(FULL, af, 2);
            au += __shfl_xor_sync(FULL, au, 2);
            af += __shfl_xor_sync(FULL, af, 4);
            au += __shfl_xor_sync(FULL, au, 4);

            const float vc  = buf ? v1 : v0;
            const float xfc = __shfl_sync(FULL, vc, lg + 0);
            const float xuc = __shfl_sync(FULL, vc, lg + 1);
            const float xmc = __shfl_sync(FULL, vc, lg + 2);

            const float f = 1.f / (1.f + __expf(-(af + xfc)));
            const float u = 1.f / (1.f + __expf(-(au + xuc)));
            const float hn = fmaf(f, h_reg, u * xmc);
            h_reg = hn;

            if (t + 1 < NS) {
                asm volatile("st.shared::cluster.f32 [%0], %1;"
                             :: "r"(rdst[buf ^ 1]), "f"(hn) : "memory");
            }

            __syncthreads();

            if (t + 1 < NS && tid < 8) {
                asm volatile("mbarrier.arrive.release.cluster.shared::cluster.b64 _, [%0];"
                             :: "r"(rmb[buf ^ 1]) : "memory");
            }

            if (kq == 0) {
                g_H[(size_t)(b * NS + t) * NM + j] = hn;
                if (t == NS - 1 && hfinal) hfinal[b * NM + j] = hn;
            }
            // chunk gate for the t+2 prefetch (crossing into a new 128-chunk)
            if ((t & 127) == 126 && t + 2 < NS)
                wait_chunk(&g_prog[b * 16 + ((t + 2) >> 7)]);
            if (active && t + 2 < NS) {
                const float nv = pxs[(size_t)(t + 2) * NM];
                if (buf) v1 = nv; else v0 = nv;
            }
        }

        CLUSTER_SYNC_();
        return;
    }

    const int lane = tid & 31;
    const int warp = tid >> 5;
    const int wm   = warp >> 1;   // 0..3
    const int wn   = warp & 1;    // 0..1
    const int lr   = tid >> 2;    // 0..63
    const int lc   = (tid & 3) * 4;

    if (blockIdx.x < 128 + PROJ_BLOCKS) {
        // ================= proj path: chunk-major (c, b, q) ==================
        const int gid  = blockIdx.x - 128;
        const int c    = gid / 96;          // chunk 0..15
        const int rem  = gid - c * 96;
        const int b    = rem / 6;           // batch 0..15
        const int q    = rem - b * 6;       // 0..5: seg = q>>1, half = q&1
        const int seg  = q >> 1;
        const int half = q & 1;
        const int bmrow = b * 16 + c;
        const int row0  = bmrow * 128;
        const int nbase = half * 128;

        const float* Bmat = (seg == 0) ? Wi : ((seg == 1) ? Wf : Wu);
        const int ldb     = (seg == 0) ? 1024 : 1280;
        const float* bias = (seg == 0) ? bi : ((seg == 1) ? bf : bu);
        float* dst        = (seg == 0) ? g_xm : ((seg == 1) ? g_xf : g_xu);
        const int NKT = 1024 / 16;

        float acc[2][8][4];
        #pragma unroll
        for (int i = 0; i < 2; i++)
            #pragma unroll
            for (int jx = 0; jx < 8; jx++)
                #pragma unroll
                for (int k = 0; k < 4; k++) acc[i][jx][k] = 0.f;

        float4 ra[2], rb[2];
        auto ldgA = [&](int kt) {
            const int kk = kt * 16 + lc;
            #pragma unroll
            for (int h = 0; h < 2; ++h)
                ra[h] = *(const float4*)(X + (size_t)(row0 + lr + h * 64) * ND + kk);
        };
        auto ldgB = [&](int kt) {
            const int kk = kt * 16 + lc;
            #pragma unroll
            for (int h = 0; h < 2; ++h)
                rb[h] = *(const float4*)(Bmat + (size_t)(nbase + lr + h * 64) * ldb + kk);
        };
        auto stsAB = [&](int buf) {
            #pragma unroll
            for (int h = 0; h < 2; ++h) {
                uint32_t* pa = &As[buf][lr + h * 64][lc];
                pa[0] = f2tf32(ra[h].x); pa[1] = f2tf32(ra[h].y);
                pa[2] = f2tf32(ra[h].z); pa[3] = f2tf32(ra[h].w);
                uint32_t* pb = &Bs[buf][lr + h * 64][lc];
                pb[0] = f2tf32(rb[h].x); pb[1] = f2tf32(rb[h].y);
                pb[2] = f2tf32(rb[h].z); pb[3] = f2tf32(rb[h].w);
            }
        };
        auto compute = [&](int buf) {
            #pragma unroll
            for (int ks = 0; ks < 2; ++ks) {
                const int k0 = ks * 8 + (lane & 3);
                uint32_t a[2][4]; uint32_t bb[8][2];
                #pragma unroll
                for (int mf = 0; mf < 2; ++mf) {
                    const int rr = wm * 32 + mf * 16 + (lane >> 2);
                    a[mf][0] = As[buf][rr    ][k0];
                    a[mf][1] = As[buf][rr + 8][k0];
                    a[mf][2] = As[buf][rr    ][k0 + 4];
                    a[mf][3] = As[buf][rr + 8][k0 + 4];
                }
                #pragma unroll
                for (int nf = 0; nf < 8; ++nf) {
                    const int cc = wn * 64 + nf * 8 + (lane >> 2);
                    bb[nf][0] = Bs[buf][cc][k0];
                    bb[nf][1] = Bs[buf][cc][k0 + 4];
                }
                #pragma unroll
                for (int mf = 0; mf < 2; ++mf)
                    #pragma unroll
                    for (int nf = 0; nf < 8; ++nf)
                        mma_tf32(acc[mf][nf], a[mf], bb[nf]);
            }
        };

        ldgA(0); ldgB(0); stsAB(0);
        __syncthreads();
        for (int kt = 0; kt < NKT; ++kt) {
            const int buf = kt & 1;
            if (kt + 1 < NKT) { ldgA(kt + 1); ldgB(kt + 1); }
            compute(buf);
            if (kt + 1 < NKT) stsAB(buf ^ 1);
            __syncthreads();
        }

        #pragma unroll
        for (int mf = 0; mf < 2; ++mf)
            #pragma unroll
            for (int nf = 0; nf < 8; ++nf)
                #pragma unroll
                for (int h = 0; h < 2; ++h) {
                    const int row = row0 + wm * 32 + mf * 16 + (lane >> 2) + h * 8;
                    const int cl  = (nbase + wn * 64 + nf * 8 + (lane & 3) * 2) & 255;
                    float v0 = acc[mf][nf][h * 2 + 0] + bias[cl];
                    float v1 = acc[mf][nf][h * 2 + 1] + bias[cl + 1];
                    if (seg == 0) {
                        v0 = v0 / (1.f + __expf(-v0));
                        v1 = v1 / (1.f + __expf(-v1));
                    }
                    *(float2*)&dst[(size_t)row * NM + cl] = make_float2(v0, v1);
                }

        // publish: stores -> fence -> (cta sync) -> release add
        __threadfence();
        __syncthreads();
        if (tid == 0) {
            asm volatile("red.release.gpu.global.add.s32 [%0], %1;"
                         :: "l"(&g_prog[bmrow]), "r"(1) : "memory");
        }
        return;
    }

    // ================= gemm1a path: out = x + bo + X @ Wo[:, :1024]^T ========
    {
        const int gid  = blockIdx.x - 128 - PROJ_BLOCKS;
        const int bm   = gid >> 3;
        const int bn   = gid & 7;
        const int row0 = bm * 128;
        const int col0 = bn * 128;
        const int NKT  = 1024 / 16;

        float acc[2][8][4];
        #pragma unroll
        for (int i = 0; i < 2; i++)
            #pragma unroll
            for (int jx = 0; jx < 8; jx++)
                #pragma unroll
                for (int k = 0; k < 4; k++) acc[i][jx][k] = 0.f;

        float4 ra[2], rb[2];
        auto ldgA = [&](int kt) {
            const int kk = kt * 16 + lc;
            #pragma unroll
            for (int h = 0; h < 2; ++h)
                ra[h] = *(const float4*)(X + (size_t)(row0 + lr + h * 64) * ND + kk);
        };
        auto ldgB = [&](int kt) {
            const int kk = kt * 16 + lc;
            #pragma unroll
            for (int h = 0; h < 2; ++h)
                rb[h] = *(const float4*)(Wo + (size_t)(col0 + lr + h * 64) * 1280 + kk);
        };
        auto stsAB = [&](int buf) {
            #pragma unroll
            for (int h = 0; h < 2; ++h) {
                uint32_t* pa = &As[buf][lr + h * 64][lc];
                pa[0] = f2tf32(ra[h].x); pa[1] = f2tf32(ra[h].y);
                pa[2] = f2tf32(ra[h].z); pa[3] = f2tf32(ra[h].w);
                uint32_t* pb = &Bs[buf][lr + h * 64][lc];
                pb[0] = f2tf32(rb[h].x); pb[1] = f2tf32(rb[h].y);
                pb[2] = f2tf32(rb[h].z); pb[3] = f2tf32(rb[h].w);
            }
        };
        auto compute = [&](int buf) {
            #pragma unroll
            for (int ks = 0; ks < 2; ++ks) {
                const int k0 = ks * 8 + (lane & 3);
                uint32_t a[2][4]; uint32_t bb[8][2];
                #pragma unroll
                for (int mf = 0; mf < 2; ++mf) {
                    const int rr = wm * 32 + mf * 16 + (lane >> 2);
                    a[mf][0] = As[buf][rr    ][k0];
                    a[mf][1] = As[buf][rr + 8][k0];
                    a[mf][2] = As[buf][rr    ][k0 + 4];
                    a[mf][3] = As[buf][rr + 8][k0 + 4];
                }
                #pragma unroll
                for (int nf = 0; nf < 8; ++nf) {
                    const int cc = wn * 64 + nf * 8 + (lane >> 2);
                    bb[nf][0] = Bs[buf][cc][k0];
                    bb[nf][1] = Bs[buf][cc][k0 + 4];
                }
                #pragma unroll
                for (int mf = 0; mf < 2; ++mf)
                    #pragma unroll
                    for (int nf = 0; nf < 8; ++nf)
                        mma_tf32(acc[mf][nf], a[mf], bb[nf]);
            }
        };

        ldgA(0); ldgB(0); stsAB(0);
        __syncthreads();
        for (int kt = 0; kt < NKT; ++kt) {
            const int buf = kt & 1;
            if (kt + 1 < NKT) { ldgA(kt + 1); ldgB(kt + 1); }
            compute(buf);
            if (kt + 1 < NKT) stsAB(buf ^ 1);
            __syncthreads();
        }

        #pragma unroll
        for (int mf = 0; mf < 2; ++mf)
            #pragma unroll
            for (int nf = 0; nf < 8; ++nf)
                #pragma unroll
                for (int h = 0; h < 2; ++h) {
                    const int row = row0 + wm * 32 + mf * 16 + (lane >> 2) + h * 8;
                    const int c0  = col0 + wn * 64 + nf * 8 + (lane & 3) * 2;
                    float v0 = acc[mf][nf][h * 2 + 0] + bo[c0]     + X[(size_t)row * ND + c0];
                    float v1 = acc[mf][nf][h * 2 + 1] + bo[c0 + 1] + X[(size_t)row * ND + c0 + 1];
                    *(float2*)&out[(size_t)row * ND + c0] = make_float2(v0, v1);
                }
    }
}

// =====================================================================
// gemm1b: out += H @ Wo[:, 1024:1280]^T   (K=256, accumulate)
// 128 threads, 4 warps, warp tile 64x64.  (unchanged, proven)
// =====================================================================
__global__ void __launch_bounds__(128, 1) gemm_h_kernel(
    const float* __restrict__ Wo, float* __restrict__ out)
{
    __shared__ uint32_t As[2][128][20];
    __shared__ uint32_t Bs[2][128][20];

    const int tid  = threadIdx.x;
    const int lane = tid & 31;
    const int warp = tid >> 5;
    const int wm   = warp >> 1;
    const int wn   = warp & 1;
    const int row0 = blockIdx.x * 128;
    const int col0 = blockIdx.y * 128;
    const int NKT  = 256 / 16;

    const int lr = tid >> 2;
    const int lc = (tid & 3) * 4;

    float acc[4][8][4];
    #pragma unroll
    for (int i = 0; i < 4; i++)
        #pragma unroll
        for (int j = 0; j < 8; j++)
            #pragma unroll
            for (int k = 0; k < 4; k++) acc[i][j][k] = 0.f;

    float4 ra[4], rb[4];
    auto ldgA = [&](int kt) {
        const int kk = kt * 16 + lc;
        #pragma unroll
        for (int h = 0; h < 4; ++h)
            ra[h] = *(const float4*)(g_H + (size_t)(row0 + lr + h * 32) * NM + kk);
    };
    auto ldgB = [&](int kt) {
        const int kk = kt * 16 + lc;
        #pragma unroll
        for (int h = 0; h < 4; ++h)
            rb[h] = *(const float4*)(Wo + (size_t)(col0 + lr + h * 32) * 1280 + 1024 + kk);
    };
    auto stsAB = [&](int buf) {
        #pragma unroll
        for (int h = 0; h < 4; ++h) {
            uint32_t* pa = &As[buf][lr + h * 32][lc];
            pa[0] = f2tf32(ra[h].x); pa[1] = f2tf32(ra[h].y);
            pa[2] = f2tf32(ra[h].z); pa[3] = f2tf32(ra[h].w);
            uint32_t* pb = &Bs[buf][lr + h * 32][lc];
            pb[0] = f2tf32(rb[h].x); pb[1] = f2tf32(rb[h].y);
            pb[2] = f2tf32(rb[h].z); pb[3] = f2tf32(rb[h].w);
        }
    };
    auto compute = [&](int buf) {
        #pragma unroll
        for (int ks = 0; ks < 2; ++ks) {
            const int k0 = ks * 8 + (lane & 3);
            uint32_t a[4][4]; uint32_t bb[8][2];
            #pragma unroll
            for (int mf = 0; mf < 4; ++mf) {
                const int r = wm * 64 + mf * 16 + (lane >> 2);
                a[mf][0] = As[buf][r    ][k0];
                a[mf][1] = As[buf][r + 8][k0];
                a[mf][2] = As[buf][r    ][k0 + 4];
                a[mf][3] = As[buf][r + 8][k0 + 4];
            }
            #pragma unroll
            for (int nf = 0; nf < 8; ++nf) {
                const int c = wn * 64 + nf * 8 + (lane >> 2);
                bb[nf][0] = Bs[buf][c][k0];
                bb[nf][1] = Bs[buf][c][k0 + 4];
            }
            #pragma unroll
            for (int mf = 0; mf < 4; ++mf)
                #pragma unroll
                for (int nf = 0; nf < 8; ++nf)
                    mma_tf32(acc[mf][nf], a[mf], bb[nf]);
        }
    };

    ldgA(0); ldgB(0); stsAB(0);
    __syncthreads();
    for (int kt = 0; kt < NKT; ++kt) {
        const int buf = kt & 1;
        if (kt + 1 < NKT) { ldgA(kt + 1); ldgB(kt + 1); }
        compute(buf);
        if (kt + 1 < NKT) stsAB(buf ^ 1);
        __syncthreads();
    }

    #pragma unroll
    for (int mf = 0; mf < 4; ++mf)
        #pragma unroll
        for (int nf = 0; nf < 8; ++nf)
            #pragma unroll
            for (int h = 0; h < 2; ++h) {
                const int row = row0 + wm * 64 + mf * 16 + (lane >> 2) + h * 8;
                const int c0  = col0 + wn * 64 + nf * 8 + (lane & 3) * 2;
                float2 cur = *(float2*)&out[(size_t)row * ND + c0];
                cur.x += acc[mf][nf][h * 2 + 0];
                cur.y += acc[mf][nf][h * 2 + 1];
                *(float2*)&out[(size_t)row * ND + c0] = cur;
            }
}

// =====================================================================
extern "C" void kernel_launch(void* const* d_in, const int* in_sizes, int n_in,
                              void* d_out, int out_size)
{
    const float* x  = (const float*)d_in[0];
    const float* Wi = (const float*)d_in[1];
    const float* bi = (const float*)d_in[2];
    const float* Wf = (const float*)d_in[3];
    const float* bf = (const float*)d_in[4];
    const float* Wu = (const float*)d_in[5];
    const float* bu = (const float*)d_in[6];
    const float* Wo = (const float*)d_in[7];
    const float* bo = (const float*)d_in[8];
    float* out = (float*)d_out;

    float* hfinal = nullptr;
    if ((long long)out_size >= (long long)NROWS * ND + (long long)NB * NM)
        hfinal = out + (size_t)NROWS * ND;

    // Phase 0: reset proj progress counters (graph-replay determinism)
    clear_prog_kernel<<<1, 256>>>();

    // Phase 1: megakernel = recurrence + proj (gated) + gemm1a (hidden)
    megakernel<<<128 + PROJ_BLOCKS + GEMM1A_BLOCKS, 256>>>(
        x, Wi, bi, Wf, bf, Wu, bu, Wo, bo, hfinal, out);

    // Phase 2: out += H @ Wo[:, 1024:]^T  (K=256)
    gemm_h_kernel<<<dim3(NROWS / 128, 8), 128>>>(Wo, out);
}

// round 12
// speedup vs baseline: 2.4451x; 1.0142x over previous
#include <cuda_runtime.h>
#include <cstdint>
#include <cstddef>

#define NB 16
#define NS 2048
#define ND 1024
#define NM 256
#define NROWS (NB*NS)   // 32768

// ---------------- scratch (device globals: allocation-free) ----------------
__device__ __align__(16) float g_xf[(size_t)NROWS * NM];
__device__ __align__(16) float g_xu[(size_t)NROWS * NM];
__device__ __align__(16) float g_xm[(size_t)NROWS * NM];
__device__ __align__(16) float g_H [(size_t)NROWS * NM];
__device__ int g_prog [256];   // proj progress: row-block (b*16+c), 6 tiles each
__device__ int g_hprog[256];   // H progress: row-block (b*16+c), 8 CTA arrivals

// ---------------- helpers ----------------
__device__ __forceinline__ uint32_t f2tf32(float x) {
    uint32_t r; asm("cvt.rna.tf32.f32 %0, %1;" : "=r"(r) : "f"(x)); return r;
}
__device__ __forceinline__ void mma_tf32(float c[4], const uint32_t a[4], const uint32_t b[2]) {
    asm volatile("mma.sync.aligned.m16n8k8.row.col.f32.tf32.tf32.f32 "
        "{%0,%1,%2,%3}, {%4,%5,%6,%7}, {%8,%9}, {%0,%1,%2,%3};"
        : "+f"(c[0]), "+f"(c[1]), "+f"(c[2]), "+f"(c[3])
        : "r"(a[0]), "r"(a[1]), "r"(a[2]), "r"(a[3]), "r"(b[0]), "r"(b[1]));
}
__device__ __forceinline__ uint32_t smem_u32(const void* p) {
    return (uint32_t)__cvta_generic_to_shared(p);
}
__device__ __forceinline__ unsigned long long pack2(float lo, float hi) {
    unsigned long long r;
    asm("mov.b64 %0, {%1, %2};" : "=l"(r) : "f"(lo), "f"(hi));
    return r;
}
__device__ __forceinline__ void unpack2(float& lo, float& hi, unsigned long long v) {
    asm("mov.b64 {%0, %1}, %2;" : "=f"(lo), "=f"(hi) : "l"(v));
}
#define FFMA2(acc, a, b) \
    asm("fma.rn.f32x2 %0, %1, %2, %0;" : "+l"(acc) : "l"(a), "l"(b))

#define CLUSTER_SYNC_() do {                                          \
    asm volatile("barrier.cluster.arrive.aligned;" ::: "memory");     \
    asm volatile("barrier.cluster.wait.aligned;"   ::: "memory");     \
} while (0)

#define MBAR_INIT(addr, cnt) \
    asm volatile("mbarrier.init.shared.b64 [%0], %1;" :: "r"(addr), "r"(cnt) : "memory")

#define MBAR_WAIT_CL(addr, par) do {                                         \
    uint32_t _m = (addr); uint32_t _p = (par); uint32_t _done;               \
    asm volatile(                                                            \
        "{\n\t.reg .pred p;\n\t"                                             \
        "mbarrier.try_wait.parity.acquire.cluster.shared::cta.b64 p, [%1], %2;\n\t" \
        "selp.b32 %0, 1, 0, p;\n\t}"                                         \
        : "=r"(_done) : "r"(_m), "r"(_p) : "memory");                        \
    if (!_done) {                                                            \
        asm volatile(                                                        \
            "{\n\t.reg .pred P1;\n\t"                                        \
            "WAIT_LOOP_%=:\n\t"                                              \
            "mbarrier.try_wait.parity.acquire.cluster.shared::cta.b64 P1, [%0], %1, 0x989680;\n\t" \
            "@P1 bra.uni WAIT_DONE_%=;\n\t"                                  \
            "bra.uni WAIT_LOOP_%=;\n\t"                                      \
            "WAIT_DONE_%=:\n\t}"                                             \
            :: "r"(_m), "r"(_p) : "memory");                                 \
    }                                                                        \
} while (0)

// spin until *cptr >= target (acquire: producer stores then visible)
__device__ __forceinline__ void wait_cnt(const int* cptr, int target) {
    int v;
    while (true) {
        asm volatile("ld.global.acquire.gpu.b32 %0, [%1];" : "=r"(v) : "l"(cptr));
        if (v >= target) break;
        __nanosleep(64);
    }
}

// =====================================================================
// clear progress counters (graph replays must start from zero)
// =====================================================================
__global__ void clear_prog_kernel() {
    g_prog[threadIdx.x]  = 0;
    g_hprog[threadIdx.x] = 0;
}

// =====================================================================
// MEGAKERNEL. Block roles by blockIdx.x:
//   [0, 128)          recurrence: 16 clusters x 8 CTAs; gated per
//                     128-step chunk on g_prog; publishes g_hprog
//   [128, 1664)       proj tiles: {xm|xf|xu} = act(X @ W^T + b),
//                     chunk-major; each tile bumps g_prog
//   [1664, 3712)      out tiles: out = x + bo + [X|H] @ Wo^T  (K=1280);
//                     X-part immediately, H-part gated on g_hprog;
//                     chunk-major order
// =====================================================================
#define PROJ_BLOCKS 1536
#define OUT_BLOCKS  2048

__global__ void __cluster_dims__(8, 1, 1) __launch_bounds__(256, 2)
megakernel(
    const float* __restrict__ X,
    const float* __restrict__ Wi, const float* __restrict__ bi,
    const float* __restrict__ Wf, const float* __restrict__ bf,
    const float* __restrict__ Wu, const float* __restrict__ bu,
    const float* __restrict__ Wo, const float* __restrict__ bo,
    float* __restrict__ hfinal, float* __restrict__ out)
{
    __shared__ uint32_t As[2][128][20];
    __shared__ uint32_t Bs[2][128][20];
    __shared__ alignas(16) float h_sm[2][256];
    __shared__ alignas(8) unsigned long long mbar[2];

    const int tid = threadIdx.x;

    if (blockIdx.x < 128) {
        // ================= recurrence path ==================================
        const int jj  = tid >> 3;
        const int kq  = tid & 7;
        const int r   = blockIdx.x & 7;
        const int b   = blockIdx.x >> 3;
        const int j   = r * 32 + jj;
        const int lg  = (tid & 31) & ~7;

        unsigned long long wf2[16], wu2[16];
        {
            const float* pf = Wf + (size_t)j * 1280 + 1024 + 4 * kq;
            const float* pu = Wu + (size_t)j * 1280 + 1024 + 4 * kq;
            #pragma unroll
            for (int i = 0; i < 8; ++i) {
                float4 vf = *(const float4*)(pf + i * 32);
                float4 vu = *(const float4*)(pu + i * 32);
                wf2[2*i+0] = pack2(vf.x, vf.y);
                wf2[2*i+1] = pack2(vf.z, vf.w);
                wu2[2*i+0] = pack2(vu.x, vu.y);
                wu2[2*i+1] = pack2(vu.z, vu.w);
            }
        }

        uint32_t rdst[2];
        {
            const uint32_t la0 = smem_u32(&h_sm[0][j]);
            const uint32_t la1 = smem_u32(&h_sm[1][j]);
            asm("mapa.shared::cluster.u32 %0, %1, %2;" : "=r"(rdst[0]) : "r"(la0), "r"(kq));
            asm("mapa.shared::cluster.u32 %0, %1, %2;" : "=r"(rdst[1]) : "r"(la1), "r"(kq));
        }
        uint32_t rmb[2] = {0u, 0u};
        if (tid < 8) {
            const uint32_t lm0 = smem_u32(&mbar[0]);
            const uint32_t lm1 = smem_u32(&mbar[1]);
            asm("mapa.shared::cluster.u32 %0, %1, %2;" : "=r"(rmb[0]) : "r"(lm0), "r"(tid));
            asm("mapa.shared::cluster.u32 %0, %1, %2;" : "=r"(rmb[1]) : "r"(lm1), "r"(tid));
        }
        const uint32_t ha[2] = { smem_u32(&h_sm[0][4 * kq]), smem_u32(&h_sm[1][4 * kq]) };

        const size_t base = (size_t)b * NS * NM + j;
        const bool active = (kq < 3);
        const float* pxs = (kq == 0) ? (g_xf + base)
                          : (kq == 1) ? (g_xu + base)
                          :             (g_xm + base);

        h_sm[0][tid] = 0.f;
        if (tid == 0) { MBAR_INIT(smem_u32(&mbar[0]), 8); MBAR_INIT(smem_u32(&mbar[1]), 8); }
        float h_reg = 0.f;
        __syncthreads();
        CLUSTER_SYNC_();

        wait_cnt(&g_prog[b * 16], 6);
        float v0 = 0.f, v1 = 0.f;
        if (active) { v0 = pxs[0]; v1 = pxs[NM]; }

        const unsigned FULL = 0xffffffffu;
        const uint32_t mloc[2] = { smem_u32(&mbar[0]), smem_u32(&mbar[1]) };
        int ph0 = 0, ph1 = 0;

        for (int t = 0; t < NS; ++t) {
            const int buf = t & 1;

            if (t > 0) {
                if (buf) { MBAR_WAIT_CL(mloc[1], ph1); ph1 ^= 1; }
                else     { MBAR_WAIT_CL(mloc[0], ph0); ph0 ^= 1; }
            }

            unsigned long long fa = 0ull, fb = 0ull, ua = 0ull, ub = 0ull;
            {
                const uint32_t hb = ha[buf];
                #pragma unroll
                for (int i = 0; i < 8; ++i) {
                    unsigned long long h01, h23;
                    asm volatile("ld.shared.v2.b64 {%0, %1}, [%2];"
                                 : "=l"(h01), "=l"(h23) : "r"(hb + i * 128));
                    FFMA2(fa, wf2[2*i+0], h01);
                    FFMA2(fb, wf2[2*i+1], h23);
                    FFMA2(ua, wu2[2*i+0], h01);
                    FFMA2(ub, wu2[2*i+1], h23);
                }
            }
            float f_lo, f_hi, u_lo, u_hi, t_lo, t_hi;
            unpack2(f_lo, f_hi, fa); unpack2(t_lo, t_hi, fb);
            float af = (f_lo + f_hi) + (t_lo + t_hi);
            unpack2(u_lo, u_hi, ua); unpack2(t_lo, t_hi, ub);
            float au = (u_lo + u_hi) + (t_lo + t_hi);

            af += __shfl_xor_sync(FULL, af, 1);
            au += __shfl_xor_sync(FULL, au, 1);
            af += __shfl_xor_sync(FULL, af, 2);
            au += __shfl_xor_sync(FULL, au, 2);
            af += __shfl_xor_sync(FULL, af, 4);
            au += __shfl_xor_sync(FULL, au, 4);

            const float vc  = buf ? v1 : v0;
            const float xfc = __shfl_sync(FULL, vc, lg + 0);
            const float xuc = __shfl_sync(FULL, vc, lg + 1);
            const float xmc = __shfl_sync(FULL, vc, lg + 2);

            const float f = 1.f / (1.f + __expf(-(af + xfc)));
            const float u = 1.f / (1.f + __expf(-(au + xuc)));
            const float hn = fmaf(f, h_reg, u * xmc);
            h_reg = hn;

            if (t + 1 < NS) {
                asm volatile("st.shared::cluster.f32 [%0], %1;"
                             :: "r"(rdst[buf ^ 1]), "f"(hn) : "memory");
            }

            __syncthreads();

            if (t + 1 < NS && tid < 8) {
                asm volatile("mbarrier.arrive.release.cluster.shared::cluster.b64 _, [%0];"
                             :: "r"(rmb[buf ^ 1]) : "memory");
            }

            if (kq == 0) {
                g_H[(size_t)(b * NS + t) * NM + j] = hn;
                if (t == NS - 1 && hfinal) hfinal[b * NM + j] = hn;
            }
            if ((t & 127) == 126 && t + 2 < NS)
                wait_cnt(&g_prog[b * 16 + ((t + 2) >> 7)], 6);
            if (active && t + 2 < NS) {
                const float nv = pxs[(size_t)(t + 2) * NM];
                if (buf) v1 = nv; else v0 = nv;
            }

            // publish H chunk completion (every 128 steps)
            if ((t & 127) == 127) {
                __threadfence();
                __syncthreads();
                if (tid == 0) {
                    asm volatile("red.release.gpu.global.add.s32 [%0], %1;"
                                 :: "l"(&g_hprog[b * 16 + (t >> 7)]), "r"(1) : "memory");
                }
            }
        }

        CLUSTER_SYNC_();
        return;
    }

    const int lane = tid & 31;
    const int warp = tid >> 5;
    const int wm   = warp >> 1;   // 0..3
    const int wn   = warp & 1;    // 0..1
    const int lr   = tid >> 2;    // 0..63
    const int lc   = (tid & 3) * 4;

    if (blockIdx.x < 128 + PROJ_BLOCKS) {
        // ================= proj path: chunk-major (c, b, q) ==================
        const int gid  = blockIdx.x - 128;
        const int c    = gid / 96;
        const int rem  = gid - c * 96;
        const int b    = rem / 6;
        const int q    = rem - b * 6;
        const int seg  = q >> 1;
        const int half = q & 1;
        const int bmrow = b * 16 + c;
        const int row0  = bmrow * 128;
        const int nbase = half * 128;

        const float* Bmat = (seg == 0) ? Wi : ((seg == 1) ? Wf : Wu);
        const int ldb     = (seg == 0) ? 1024 : 1280;
        const float* bias = (seg == 0) ? bi : ((seg == 1) ? bf : bu);
        float* dst        = (seg == 0) ? g_xm : ((seg == 1) ? g_xf : g_xu);
        const int NKT = 1024 / 16;

        float acc[2][8][4];
        #pragma unroll
        for (int i = 0; i < 2; i++)
            #pragma unroll
            for (int jx = 0; jx < 8; jx++)
                #pragma unroll
                for (int k = 0; k < 4; k++) acc[i][jx][k] = 0.f;

        float4 ra[2], rb[2];
        auto ldgA = [&](int kt) {
            const int kk = kt * 16 + lc;
            #pragma unroll
            for (int h = 0; h < 2; ++h)
                ra[h] = *(const float4*)(X + (size_t)(row0 + lr + h * 64) * ND + kk);
        };
        auto ldgB = [&](int kt) {
            const int kk = kt * 16 + lc;
            #pragma unroll
            for (int h = 0; h < 2; ++h)
                rb[h] = *(const float4*)(Bmat + (size_t)(nbase + lr + h * 64) * ldb + kk);
        };
        auto stsAB = [&](int buf) {
            #pragma unroll
            for (int h = 0; h < 2; ++h) {
                uint32_t* pa = &As[buf][lr + h * 64][lc];
                pa[0] = f2tf32(ra[h].x); pa[1] = f2tf32(ra[h].y);
                pa[2] = f2tf32(ra[h].z); pa[3] = f2tf32(ra[h].w);
                uint32_t* pb = &Bs[buf][lr + h * 64][lc];
                pb[0] = f2tf32(rb[h].x); pb[1] = f2tf32(rb[h].y);
                pb[2] = f2tf32(rb[h].z); pb[3] = f2tf32(rb[h].w);
            }
        };
        auto compute = [&](int buf) {
            #pragma unroll
            for (int ks = 0; ks < 2; ++ks) {
                const int k0 = ks * 8 + (lane & 3);
                uint32_t a[2][4]; uint32_t bb[8][2];
                #pragma unroll
                for (int mf = 0; mf < 2; ++mf) {
                    const int rr = wm * 32 + mf * 16 + (lane >> 2);
                    a[mf][0] = As[buf][rr    ][k0];
                    a[mf][1] = As[buf][rr + 8][k0];
                    a[mf][2] = As[buf][rr    ][k0 + 4];
                    a[mf][3] = As[buf][rr + 8][k0 + 4];
                }
                #pragma unroll
                for (int nf = 0; nf < 8; ++nf) {
                    const int cc = wn * 64 + nf * 8 + (lane >> 2);
                    bb[nf][0] = Bs[buf][cc][k0];
                    bb[nf][1] = Bs[buf][cc][k0 + 4];
                }
                #pragma unroll
                for (int mf = 0; mf < 2; ++mf)
                    #pragma unroll
                    for (int nf = 0; nf < 8; ++nf)
                        mma_tf32(acc[mf][nf], a[mf], bb[nf]);
            }
        };

        ldgA(0); ldgB(0); stsAB(0);
        __syncthreads();
        for (int kt = 0; kt < NKT; ++kt) {
            const int buf = kt & 1;
            if (kt + 1 < NKT) { ldgA(kt + 1); ldgB(kt + 1); }
            compute(buf);
            if (kt + 1 < NKT) stsAB(buf ^ 1);
            __syncthreads();
        }

        #pragma unroll
        for (int mf = 0; mf < 2; ++mf)
            #pragma unroll
            for (int nf = 0; nf < 8; ++nf)
                #pragma unroll
                for (int h = 0; h < 2; ++h) {
                    const int row = row0 + wm * 32 + mf * 16 + (lane >> 2) + h * 8;
                    const int cl  = (nbase + wn * 64 + nf * 8 + (lane & 3) * 2) & 255;
                    float v0 = acc[mf][nf][h * 2 + 0] + bias[cl];
                    float v1 = acc[mf][nf][h * 2 + 1] + bias[cl + 1];
                    if (seg == 0) {
                        v0 = v0 / (1.f + __expf(-v0));
                        v1 = v1 / (1.f + __expf(-v1));
                    }
                    *(float2*)&dst[(size_t)row * NM + cl] = make_float2(v0, v1);
                }

        __threadfence();
        __syncthreads();
        if (tid == 0) {
            asm volatile("red.release.gpu.global.add.s32 [%0], %1;"
                         :: "l"(&g_prog[bmrow]), "r"(1) : "memory");
        }
        return;
    }

    // ============ out path: out = x + bo + [X|H] @ Wo^T (K=1280) =============
    // chunk-major: gid -> c (chunk), b (batch), bn; bm = b*16+c.
    {
        const int gid = blockIdx.x - 128 - PROJ_BLOCKS;
        const int c   = gid >> 7;           // 0..15
        const int rem = gid & 127;
        const int b   = rem >> 3;           // 0..15
        const int bn  = rem & 7;            // 0..7
        const int bm  = b * 16 + c;
        const int row0 = bm * 128;
        const int col0 = bn * 128;
        const int NKT  = 1280 / 16;         // 80; k-tiles 64..79 read g_H

        float acc[2][8][4];
        #pragma unroll
        for (int i = 0; i < 2; i++)
            #pragma unroll
            for (int jx = 0; jx < 8; jx++)
                #pragma unroll
                for (int k = 0; k < 4; k++) acc[i][jx][k] = 0.f;

        float4 ra[2], rb[2];
        auto ldgA = [&](int kt) {
            const int kk = kt * 16 + lc;
            #pragma unroll
            for (int h = 0; h < 2; ++h) {
                const int rr = row0 + lr + h * 64;
                if (kk >= 1024)
                    ra[h] = *(const float4*)(g_H + (size_t)rr * NM + (kk - 1024));
                else
                    ra[h] = *(const float4*)(X + (size_t)rr * ND + kk);
            }
        };
        auto ldgB = [&](int kt) {
            const int kk = kt * 16 + lc;
            #pragma unroll
            for (int h = 0; h < 2; ++h)
                rb[h] = *(const float4*)(Wo + (size_t)(col0 + lr + h * 64) * 1280 + kk);
        };
        auto stsAB = [&](int buf) {
            #pragma unroll
            for (int h = 0; h < 2; ++h) {
                uint32_t* pa = &As[buf][lr + h * 64][lc];
                pa[0] = f2tf32(ra[h].x); pa[1] = f2tf32(ra[h].y);
                pa[2] = f2tf32(ra[h].z); pa[3] = f2tf32(ra[h].w);
                uint32_t* pb = &Bs[buf][lr + h * 64][lc];
                pb[0] = f2tf32(rb[h].x); pb[1] = f2tf32(rb[h].y);
                pb[2] = f2tf32(rb[h].z); pb[3] = f2tf32(rb[h].w);
            }
        };
        auto compute = [&](int buf) {
            #pragma unroll
            for (int ks = 0; ks < 2; ++ks) {
                const int k0 = ks * 8 + (lane & 3);
                uint32_t a[2][4]; uint32_t bb[8][2];
                #pragma unroll
                for (int mf = 0; mf < 2; ++mf) {
                    const int rr = wm * 32 + mf * 16 + (lane >> 2);
                    a[mf][0] = As[buf][rr    ][k0];
                    a[mf][1] = As[buf][rr + 8][k0];
                    a[mf][2] = As[buf][rr    ][k0 + 4];
                    a[mf][3] = As[buf][rr + 8][k0 + 4];
                }
                #pragma unroll
                for (int nf = 0; nf < 8; ++nf) {
                    const int cc = wn * 64 + nf * 8 + (lane >> 2);
                    bb[nf][0] = Bs[buf][cc][k0];
                    bb[nf][1] = Bs[buf][cc][k0 + 4];
                }
                #pragma unroll
                for (int mf = 0; mf < 2; ++mf)
                    #pragma unroll
                    for (int nf = 0; nf < 8; ++nf)
                        mma_tf32(acc[mf][nf], a[mf], bb[nf]);
            }
        };

        ldgA(0); ldgB(0); stsAB(0);
        __syncthreads();
        for (int kt = 0; kt < NKT; ++kt) {
            const int buf = kt & 1;
            if (kt + 1 < NKT) {
                if (kt + 1 == 64) wait_cnt(&g_hprog[bm], 8);  // gate H-part
                ldgA(kt + 1); ldgB(kt + 1);
            }
            compute(buf);
            if (kt + 1 < NKT) stsAB(buf ^ 1);
            __syncthreads();
        }

        #pragma unroll
        for (int mf = 0; mf < 2; ++mf)
            #pragma unroll
            for (int nf = 0; nf < 8; ++nf)
                #pragma unroll
                for (int h = 0; h < 2; ++h) {
                    const int row = row0 + wm * 32 + mf * 16 + (lane >> 2) + h * 8;
                    const int c0  = col0 + wn * 64 + nf * 8 + (lane & 3) * 2;
                    float v0 = acc[mf][nf][h * 2 + 0] + bo[c0]     + X[(size_t)row * ND + c0];
                    float v1 = acc[mf][nf][h * 2 + 1] + bo[c0 + 1] + X[(size_t)row * ND + c0 + 1];
                    *(float2*)&out[(size_t)row * ND + c0] = make_float2(v0, v1);
                }
    }
}

// =====================================================================
extern "C" void kernel_launch(void* const* d_in, const int* in_sizes, int n_in,
                              void* d_out, int out_size)
{
    const float* x  = (const float*)d_in[0];
    const float* Wi = (const float*)d_in[1];
    const float* bi = (const float*)d_in[2];
    const float* Wf = (const float*)d_in[3];
    const float* bf = (const float*)d_in[4];
    const float* Wu = (const float*)d_in[5];
    const float* bu = (const float*)d_in[6];
    const float* Wo = (const float*)d_in[7];
    const float* bo = (const float*)d_in[8];
    float* out = (float*)d_out;

    float* hfinal = nullptr;
    if ((long long)out_size >= (long long)NROWS * ND + (long long)NB * NM)
        hfinal = out + (size_t)NROWS * ND;

    // Phase 0: reset progress counters (graph-replay determinism)
    clear_prog_kernel<<<1, 256>>>();

    // Phase 1: megakernel = recurrence + proj (gated) + out tiles (gated)
    megakernel<<<128 + PROJ_BLOCKS + OUT_BLOCKS, 256>>>(
        x, Wi, bi, Wf, bf, Wu, bu, Wo, bo, hfinal, out);
}

// round 13
// speedup vs baseline: 2.5061x; 1.0249x over previous
#include <cuda_runtime.h>
#include <cstdint>
#include <cstddef>

#define NB 16
#define NS 2048
#define ND 1024
#define NM 256
#define NROWS (NB*NS)   // 32768

// ---------------- scratch (device globals: allocation-free) ----------------
__device__ __align__(16) float g_xf[(size_t)NROWS * NM];
__device__ __align__(16) float g_xu[(size_t)NROWS * NM];
__device__ __align__(16) float g_xm[(size_t)NROWS * NM];
__device__ __align__(16) float g_H [(size_t)NROWS * NM];
__device__ int g_prog [256];   // proj progress: row-block (b*16+c), target 6
__device__ int g_hprog[256];   // H progress: row-block (b*16+c), target 4

// ---------------- dynamic smem layout ----------------
// GEMM pair-blocks: As[2][128][20] @0 (20480B), Bs_half0 @20480, Bs_half1 @40960
// Recurrence:       h_sm[2][256] @0 (2048B), mbar[2] @2048
#define DSM_AS    0
#define DSM_BS    20480
#define DSM_TOTAL 61440

// ---------------- helpers ----------------
__device__ __forceinline__ uint32_t f2tf32(float x) {
    uint32_t r; asm("cvt.rna.tf32.f32 %0, %1;" : "=r"(r) : "f"(x)); return r;
}
__device__ __forceinline__ void mma_tf32(float c[4], const uint32_t a[4], const uint32_t b[2]) {
    asm volatile("mma.sync.aligned.m16n8k8.row.col.f32.tf32.tf32.f32 "
        "{%0,%1,%2,%3}, {%4,%5,%6,%7}, {%8,%9}, {%0,%1,%2,%3};"
        : "+f"(c[0]), "+f"(c[1]), "+f"(c[2]), "+f"(c[3])
        : "r"(a[0]), "r"(a[1]), "r"(a[2]), "r"(a[3]), "r"(b[0]), "r"(b[1]));
}
__device__ __forceinline__ uint32_t smem_u32(const void* p) {
    return (uint32_t)__cvta_generic_to_shared(p);
}
__device__ __forceinline__ unsigned long long pack2(float lo, float hi) {
    unsigned long long r;
    asm("mov.b64 %0, {%1, %2};" : "=l"(r) : "f"(lo), "f"(hi));
    return r;
}
__device__ __forceinline__ void unpack2(float& lo, float& hi, unsigned long long v) {
    asm("mov.b64 {%0, %1}, %2;" : "=f"(lo), "=f"(hi) : "l"(v));
}
#define FFMA2(acc, a, b) \
    asm("fma.rn.f32x2 %0, %1, %2, %0;" : "+l"(acc) : "l"(a), "l"(b))

#define CLUSTER_SYNC_() do {                                          \
    asm volatile("barrier.cluster.arrive.aligned;" ::: "memory");     \
    asm volatile("barrier.cluster.wait.aligned;"   ::: "memory");     \
} while (0)

#define MBAR_INIT(addr, cnt) \
    asm volatile("mbarrier.init.shared.b64 [%0], %1;" :: "r"(addr), "r"(cnt) : "memory")

#define MBAR_WAIT_CL(addr, par) do {                                         \
    uint32_t _m = (addr); uint32_t _p = (par); uint32_t _done;               \
    asm volatile(                                                            \
        "{\n\t.reg .pred p;\n\t"                                             \
        "mbarrier.try_wait.parity.acquire.cluster.shared::cta.b64 p, [%1], %2;\n\t" \
        "selp.b32 %0, 1, 0, p;\n\t}"                                         \
        : "=r"(_done) : "r"(_m), "r"(_p) : "memory");                        \
    if (!_done) {                                                            \
        asm volatile(                                                        \
            "{\n\t.reg .pred P1;\n\t"                                        \
            "WAIT_LOOP_%=:\n\t"                                              \
            "mbarrier.try_wait.parity.acquire.cluster.shared::cta.b64 P1, [%0], %1, 0x989680;\n\t" \
            "@P1 bra.uni WAIT_DONE_%=;\n\t"                                  \
            "bra.uni WAIT_LOOP_%=;\n\t"                                      \
            "WAIT_DONE_%=:\n\t}"                                             \
            :: "r"(_m), "r"(_p) : "memory");                                 \
    }                                                                        \
} while (0)

// spin until *cptr >= target (acquire: producer stores then visible)
__device__ __forceinline__ void wait_cnt(const int* cptr, int target) {
    int v;
    while (true) {
        asm volatile("ld.global.acquire.gpu.b32 %0, [%1];" : "=r"(v) : "l"(cptr));
        if (v >= target) break;
        __nanosleep(64);
    }
}

__global__ void clear_prog_kernel() {
    g_prog[threadIdx.x]  = 0;
    g_hprog[threadIdx.x] = 0;
}

// =====================================================================
// MEGAKERNEL v2 — 512-thread blocks, cluster 4, dynamic smem.
//   [0, 64)      recurrence: 16 clusters x 4 CTAs x 512 thr, 64 rows/CTA.
//                Exclusive SM (regs fill RF). Gated on g_prog; publishes
//                g_hprog (target 4).
//   [64, 832)    proj PAIR tiles: one 128-row chunk x {seg: both halves}.
//                A smem shared between halves. Bumps g_prog by 2.
//   [832, 1856)  out PAIR tiles: out = x + bo + [X|H] @ Wo^T, two bn
//                columns per block; H-part gated on g_hprog == 4.
// =====================================================================
#define REC_BLOCKS  64
#define PROJ_PAIRS  768
#define OUT_PAIRS   1024

__global__ void __cluster_dims__(4, 1, 1) __launch_bounds__(512, 1)
megakernel(
    const float* __restrict__ X,
    const float* __restrict__ Wi, const float* __restrict__ bi,
    const float* __restrict__ Wf, const float* __restrict__ bf,
    const float* __restrict__ Wu, const float* __restrict__ bu,
    const float* __restrict__ Wo, const float* __restrict__ bo,
    float* __restrict__ hfinal, float* __restrict__ out)
{
    extern __shared__ char dsm[];
    const int tid = threadIdx.x;

    if (blockIdx.x < REC_BLOCKS) {
        // ================= recurrence: 4-CTA cluster, 512 threads ===========
        float* h_sm = (float*)dsm;                          // [2][256]
        unsigned long long* mbar = (unsigned long long*)(dsm + 2048);

        const int jj = tid >> 3;          // local row 0..63
        const int kq = tid & 7;           // k interleave; dest CTA = kq (<4)
        const int r  = blockIdx.x & 3;    // cluster rank
        const int b  = blockIdx.x >> 2;   // batch
        const int j  = r * 64 + jj;       // global row
        const int lg = (tid & 31) & ~7;

        unsigned long long wf2[16], wu2[16];
        {
            const float* pf = Wf + (size_t)j * 1280 + 1024 + 4 * kq;
            const float* pu = Wu + (size_t)j * 1280 + 1024 + 4 * kq;
            #pragma unroll
            for (int i = 0; i < 8; ++i) {
                float4 vf = *(const float4*)(pf + i * 32);
                float4 vu = *(const float4*)(pu + i * 32);
                wf2[2*i+0] = pack2(vf.x, vf.y);
                wf2[2*i+1] = pack2(vf.z, vf.w);
                wu2[2*i+0] = pack2(vu.x, vu.y);
                wu2[2*i+1] = pack2(vu.z, vu.w);
            }
        }

        uint32_t rdst[2] = {0u, 0u};
        if (kq < 4) {
            const uint32_t la0 = smem_u32(&h_sm[j]);
            const uint32_t la1 = smem_u32(&h_sm[256 + j]);
            asm("mapa.shared::cluster.u32 %0, %1, %2;" : "=r"(rdst[0]) : "r"(la0), "r"(kq));
            asm("mapa.shared::cluster.u32 %0, %1, %2;" : "=r"(rdst[1]) : "r"(la1), "r"(kq));
        }
        uint32_t rmb[2] = {0u, 0u};
        if (tid < 4) {
            const uint32_t lm0 = smem_u32(&mbar[0]);
            const uint32_t lm1 = smem_u32(&mbar[1]);
            asm("mapa.shared::cluster.u32 %0, %1, %2;" : "=r"(rmb[0]) : "r"(lm0), "r"(tid));
            asm("mapa.shared::cluster.u32 %0, %1, %2;" : "=r"(rmb[1]) : "r"(lm1), "r"(tid));
        }
        const uint32_t ha[2] = { smem_u32(&h_sm[4 * kq]), smem_u32(&h_sm[256 + 4 * kq]) };

        const size_t base = (size_t)b * NS * NM + j;
        const bool active = (kq < 3);
        const float* pxs = (kq == 0) ? (g_xf + base)
                          : (kq == 1) ? (g_xu + base)
                          :             (g_xm + base);

        if (tid < 256) h_sm[tid] = 0.f;
        if (tid == 0) { MBAR_INIT(smem_u32(&mbar[0]), 4); MBAR_INIT(smem_u32(&mbar[1]), 4); }
        float h_reg = 0.f;
        __syncthreads();
        CLUSTER_SYNC_();

        wait_cnt(&g_prog[b * 16], 6);
        float v0 = 0.f, v1 = 0.f;
        if (active) { v0 = pxs[0]; v1 = pxs[NM]; }

        const unsigned FULL = 0xffffffffu;
        const uint32_t mloc[2] = { smem_u32(&mbar[0]), smem_u32(&mbar[1]) };
        int ph0 = 0, ph1 = 0;

        for (int t = 0; t < NS; ++t) {
            const int buf = t & 1;

            if (t > 0) {
                if (buf) { MBAR_WAIT_CL(mloc[1], ph1); ph1 ^= 1; }
                else     { MBAR_WAIT_CL(mloc[0], ph0); ph0 ^= 1; }
            }

            unsigned long long fa = 0ull, fb = 0ull, ua = 0ull, ub = 0ull;
            {
                const uint32_t hb = ha[buf];
                #pragma unroll
                for (int i = 0; i < 8; ++i) {
                    unsigned long long h01, h23;
                    asm volatile("ld.shared.v2.b64 {%0, %1}, [%2];"
                                 : "=l"(h01), "=l"(h23) : "r"(hb + i * 128));
                    FFMA2(fa, wf2[2*i+0], h01);
                    FFMA2(fb, wf2[2*i+1], h23);
                    FFMA2(ua, wu2[2*i+0], h01);
                    FFMA2(ub, wu2[2*i+1], h23);
                }
            }
            float f_lo, f_hi, u_lo, u_hi, t_lo, t_hi;
            unpack2(f_lo, f_hi, fa); unpack2(t_lo, t_hi, fb);
            float af = (f_lo + f_hi) + (t_lo + t_hi);
            unpack2(u_lo, u_hi, ua); unpack2(t_lo, t_hi, ub);
            float au = (u_lo + u_hi) + (t_lo + t_hi);

            af += __shfl_xor_sync(FULL, af, 1);
            au += __shfl_xor_sync(FULL, au, 1);
            af += __shfl_xor_sync(FULL, af, 2);
            au += __shfl_xor_sync(FULL, au, 2);
            af += __shfl_xor_sync(FULL, af, 4);
            au += __shfl_xor_sync(FULL, au, 4);

            const float vc  = buf ? v1 : v0;
            const float xfc = __shfl_sync(FULL, vc, lg + 0);
            const float xuc = __shfl_sync(FULL, vc, lg + 1);
            const float xmc = __shfl_sync(FULL, vc, lg + 2);

            const float f = 1.f / (1.f + __expf(-(af + xfc)));
            const float u = 1.f / (1.f + __expf(-(au + xuc)));
            const float hn = fmaf(f, h_reg, u * xmc);
            h_reg = hn;

            if (kq < 4 && t + 1 < NS) {
                asm volatile("st.shared::cluster.f32 [%0], %1;"
                             :: "r"(rdst[buf ^ 1]), "f"(hn) : "memory");
            }

            __syncthreads();   // all remote stores issued + reads of buf done

            if (t + 1 < NS && tid < 4) {
                asm volatile("mbarrier.arrive.release.cluster.shared::cluster.b64 _, [%0];"
                             :: "r"(rmb[buf ^ 1]) : "memory");
            }

            if (kq == 0) {
                g_H[(size_t)(b * NS + t) * NM + j] = hn;
                if (t == NS - 1 && hfinal) hfinal[b * NM + j] = hn;
            }
            if ((t & 127) == 126 && t + 2 < NS)
                wait_cnt(&g_prog[b * 16 + ((t + 2) >> 7)], 6);
            if (active && t + 2 < NS) {
                const float nv = pxs[(size_t)(t + 2) * NM];
                if (buf) v1 = nv; else v0 = nv;
            }

            if ((t & 127) == 127) {
                __threadfence();
                __syncthreads();
                if (tid == 0) {
                    asm volatile("red.release.gpu.global.add.s32 [%0], %1;"
                                 :: "l"(&g_hprog[b * 16 + (t >> 7)]), "r"(1) : "memory");
                }
            }
        }

        CLUSTER_SYNC_();
        return;
    }

    // =============== GEMM pair-block common setup (512 thr = 2 tiles) =======
    const int half = tid >> 8;        // 0 or 1 -> which tile of the pair
    const int htid = tid & 255;
    const int lane = htid & 31;
    const int warp = htid >> 5;       // 0..7 within half
    const int wm   = warp >> 1;       // 0..3
    const int wn   = warp & 1;        // 0..1
    const int lr   = htid >> 2;       // 0..63
    const int lc   = (htid & 3) * 4;

    uint32_t* As = (uint32_t*)(dsm + DSM_AS);                  // [2][128][20]
    uint32_t* Bs = (uint32_t*)(dsm + DSM_BS + half * 20480);   // per-half [2][128][20]

    if (blockIdx.x < REC_BLOCKS + PROJ_PAIRS) {
        // ================= proj pair: chunk-major (c, b, seg) ================
        const int gid = blockIdx.x - REC_BLOCKS;   // 0..767
        const int c   = gid / 48;
        const int rem = gid - c * 48;
        const int b   = rem / 3;
        const int seg = rem - b * 3;
        const int bmrow = b * 16 + c;
        const int row0  = bmrow * 128;
        const int nbase = half * 128;

        const float* Bmat = (seg == 0) ? Wi : ((seg == 1) ? Wf : Wu);
        const int ldb     = (seg == 0) ? 1024 : 1280;
        const float* bias = (seg == 0) ? bi : ((seg == 1) ? bf : bu);
        float* dst        = (seg == 0) ? g_xm : ((seg == 1) ? g_xf : g_xu);
        const int NKT = 1024 / 16;

        float acc[2][8][4];
        #pragma unroll
        for (int i = 0; i < 2; i++)
            #pragma unroll
            for (int jx = 0; jx < 8; jx++)
                #pragma unroll
                for (int k = 0; k < 4; k++) acc[i][jx][k] = 0.f;

        float4 ra[2], rb[2];
        auto ldgA = [&](int kt) {      // half 0 only
            const int kk = kt * 16 + lc;
            #pragma unroll
            for (int h = 0; h < 2; ++h)
                ra[h] = *(const float4*)(X + (size_t)(row0 + lr + h * 64) * ND + kk);
        };
        auto ldgB = [&](int kt) {      // each half loads its own B
            const int kk = kt * 16 + lc;
            #pragma unroll
            for (int h = 0; h < 2; ++h)
                rb[h] = *(const float4*)(Bmat + (size_t)(nbase + lr + h * 64) * ldb + kk);
        };
        auto stsAB = [&](int buf) {
            #pragma unroll
            for (int h = 0; h < 2; ++h) {
                if (half == 0) {
                    uint32_t* pa = As + ((size_t)buf * 128 + lr + h * 64) * 20 + lc;
                    pa[0] = f2tf32(ra[h].x); pa[1] = f2tf32(ra[h].y);
                    pa[2] = f2tf32(ra[h].z); pa[3] = f2tf32(ra[h].w);
                }
                uint32_t* pb = Bs + ((size_t)buf * 128 + lr + h * 64) * 20 + lc;
                pb[0] = f2tf32(rb[h].x); pb[1] = f2tf32(rb[h].y);
                pb[2] = f2tf32(rb[h].z); pb[3] = f2tf32(rb[h].w);
            }
        };
        auto compute = [&](int buf) {
            #pragma unroll
            for (int ks = 0; ks < 2; ++ks) {
                const int k0 = ks * 8 + (lane & 3);
                uint32_t a[2][4]; uint32_t bb[8][2];
                #pragma unroll
                for (int mf = 0; mf < 2; ++mf) {
                    const int rr = wm * 32 + mf * 16 + (lane >> 2);
                    const uint32_t* ab = As + ((size_t)buf * 128 + rr) * 20;
                    a[mf][0] = ab[k0];
                    a[mf][1] = ab[8 * 20 + k0];
                    a[mf][2] = ab[k0 + 4];
                    a[mf][3] = ab[8 * 20 + k0 + 4];
                }
                #pragma unroll
                for (int nf = 0; nf < 8; ++nf) {
                    const int cc = wn * 64 + nf * 8 + (lane >> 2);
                    const uint32_t* bbp = Bs + ((size_t)buf * 128 + cc) * 20;
                    bb[nf][0] = bbp[k0];
                    bb[nf][1] = bbp[k0 + 4];
                }
                #pragma unroll
                for (int mf = 0; mf < 2; ++mf)
                    #pragma unroll
                    for (int nf = 0; nf < 8; ++nf)
                        mma_tf32(acc[mf][nf], a[mf], bb[nf]);
            }
        };

        if (half == 0) ldgA(0);
        ldgB(0);
        stsAB(0);
        __syncthreads();
        for (int kt = 0; kt < NKT; ++kt) {
            const int buf = kt & 1;
            if (kt + 1 < NKT) { if (half == 0) ldgA(kt + 1); ldgB(kt + 1); }
            compute(buf);
            if (kt + 1 < NKT) stsAB(buf ^ 1);
            __syncthreads();
        }

        #pragma unroll
        for (int mf = 0; mf < 2; ++mf)
            #pragma unroll
            for (int nf = 0; nf < 8; ++nf)
                #pragma unroll
                for (int h = 0; h < 2; ++h) {
                    const int row = row0 + wm * 32 + mf * 16 + (lane >> 2) + h * 8;
                    const int cl  = (nbase + wn * 64 + nf * 8 + (lane & 3) * 2) & 255;
                    float v0 = acc[mf][nf][h * 2 + 0] + bias[cl];
                    float v1 = acc[mf][nf][h * 2 + 1] + bias[cl + 1];
                    if (seg == 0) {
                        v0 = v0 / (1.f + __expf(-v0));
                        v1 = v1 / (1.f + __expf(-v1));
                    }
                    *(float2*)&dst[(size_t)row * NM + cl] = make_float2(v0, v1);
                }

        __threadfence();
        __syncthreads();
        if (tid == 0) {
            asm volatile("red.release.gpu.global.add.s32 [%0], %1;"
                         :: "l"(&g_prog[bmrow]), "r"(2) : "memory");
        }
        return;
    }

    // ============ out pair: out = x + bo + [X|H] @ Wo^T (K=1280) =============
    {
        const int gid = blockIdx.x - REC_BLOCKS - PROJ_PAIRS;  // 0..1023
        const int c   = gid >> 6;            // chunk 0..15
        const int rem = gid & 63;
        const int b   = rem >> 2;            // batch 0..15
        const int bnp = rem & 3;             // bn pair 0..3
        const int bm  = b * 16 + c;
        const int row0 = bm * 128;
        const int col0 = (bnp * 2 + half) * 128;
        const int NKT  = 1280 / 16;          // 80; kt >= 64 reads g_H

        float acc[2][8][4];
        #pragma unroll
        for (int i = 0; i < 2; i++)
            #pragma unroll
            for (int jx = 0; jx < 8; jx++)
                #pragma unroll
                for (int k = 0; k < 4; k++) acc[i][jx][k] = 0.f;

        float4 ra[2], rb[2];
        auto ldgA = [&](int kt) {      // half 0 only
            const int kk = kt * 16 + lc;
            #pragma unroll
            for (int h = 0; h < 2; ++h) {
                const int rr = row0 + lr + h * 64;
                if (kk >= 1024)
                    ra[h] = *(const float4*)(g_H + (size_t)rr * NM + (kk - 1024));
                else
                    ra[h] = *(const float4*)(X + (size_t)rr * ND + kk);
            }
        };
        auto ldgB = [&](int kt) {
            const int kk = kt * 16 + lc;
            #pragma unroll
            for (int h = 0; h < 2; ++h)
                rb[h] = *(const float4*)(Wo + (size_t)(col0 + lr + h * 64) * 1280 + kk);
        };
        auto stsAB = [&](int buf) {
            #pragma unroll
            for (int h = 0; h < 2; ++h) {
                if (half == 0) {
                    uint32_t* pa = As + ((size_t)buf * 128 + lr + h * 64) * 20 + lc;
                    pa[0] = f2tf32(ra[h].x); pa[1] = f2tf32(ra[h].y);
                    pa[2] = f2tf32(ra[h].z); pa[3] = f2tf32(ra[h].w);
                }
                uint32_t* pb = Bs + ((size_t)buf * 128 + lr + h * 64) * 20 + lc;
                pb[0] = f2tf32(rb[h].x); pb[1] = f2tf32(rb[h].y);
                pb[2] = f2tf32(rb[h].z); pb[3] = f2tf32(rb[h].w);
            }
        };
        auto compute = [&](int buf) {
            #pragma unroll
            for (int ks = 0; ks < 2; ++ks) {
                const int k0 = ks * 8 + (lane & 3);
                uint32_t a[2][4]; uint32_t bb[8][2];
                #pragma unroll
                for (int mf = 0; mf < 2; ++mf) {
                    const int rr = wm * 32 + mf * 16 + (lane >> 2);
                    const uint32_t* ab = As + ((size_t)buf * 128 + rr) * 20;
                    a[mf][0] = ab[k0];
                    a[mf][1] = ab[8 * 20 + k0];
                    a[mf][2] = ab[k0 + 4];
                    a[mf][3] = ab[8 * 20 + k0 + 4];
                }
                #pragma unroll
                for (int nf = 0; nf < 8; ++nf) {
                    const int cc = wn * 64 + nf * 8 + (lane >> 2);
                    const uint32_t* bbp = Bs + ((size_t)buf * 128 + cc) * 20;
                    bb[nf][0] = bbp[k0];
                    bb[nf][1] = bbp[k0 + 4];
                }
                #pragma unroll
                for (int mf = 0; mf < 2; ++mf)
                    #pragma unroll
                    for (int nf = 0; nf < 8; ++nf)
                        mma_tf32(acc[mf][nf], a[mf], bb[nf]);
            }
        };

        if (half == 0) ldgA(0);
        ldgB(0);
        stsAB(0);
        __syncthreads();
        for (int kt = 0; kt < NKT; ++kt) {
            const int buf = kt & 1;
            if (kt + 1 < NKT) {
                if (kt + 1 == 64) wait_cnt(&g_hprog[bm], 4);   // gate H-part
                if (half == 0) ldgA(kt + 1);
                ldgB(kt + 1);
            }
            compute(buf);
            if (kt + 1 < NKT) stsAB(buf ^ 1);
            __syncthreads();
        }

        #pragma unroll
        for (int mf = 0; mf < 2; ++mf)
            #pragma unroll
            for (int nf = 0; nf < 8; ++nf)
                #pragma unroll
                for (int h = 0; h < 2; ++h) {
                    const int row = row0 + wm * 32 + mf * 16 + (lane >> 2) + h * 8;
                    const int c0  = col0 + wn * 64 + nf * 8 + (lane & 3) * 2;
                    float v0 = acc[mf][nf][h * 2 + 0] + bo[c0]     + X[(size_t)row * ND + c0];
                    float v1 = acc[mf][nf][h * 2 + 1] + bo[c0 + 1] + X[(size_t)row * ND + c0 + 1];
                    *(float2*)&out[(size_t)row * ND + c0] = make_float2(v0, v1);
                }
    }
}

// =====================================================================
extern "C" void kernel_launch(void* const* d_in, const int* in_sizes, int n_in,
                              void* d_out, int out_size)
{
    const float* x  = (const float*)d_in[0];
    const float* Wi = (const float*)d_in[1];
    const float* bi = (const float*)d_in[2];
    const float* Wf = (const float*)d_in[3];
    const float* bf = (const float*)d_in[4];
    const float* Wu = (const float*)d_in[5];
    const float* bu = (const float*)d_in[6];
    const float* Wo = (const float*)d_in[7];
    const float* bo = (const float*)d_in[8];
    float* out = (float*)d_out;

    float* hfinal = nullptr;
    if ((long long)out_size >= (long long)NROWS * ND + (long long)NB * NM)
        hfinal = out + (size_t)NROWS * ND;

    cudaFuncSetAttribute(megakernel,
                         cudaFuncAttributeMaxDynamicSharedMemorySize, DSM_TOTAL);

    clear_prog_kernel<<<1, 256>>>();
    megakernel<<<REC_BLOCKS + PROJ_PAIRS + OUT_PAIRS, 512, DSM_TOTAL>>>(
        x, Wi, bi, Wf, bf, Wu, bu, Wo, bo, hfinal, out);
}